// round 10
// baseline (speedup 1.0000x reference)
#include <cuda_runtime.h>
#include <cuda_bf16.h>
#include <cstdint>

// ---------------- problem constants ----------------
#define B_    2
#define L_    4096
#define DM    2048      // d_model
#define DSSM  4096
#define DST   128       // d_state
#define NH    64        // heads
#define HD    64        // headdim
#define DCONV 4
#define CHK   64        // chunk length
#define NC    64        // num chunks (L/CHK)
#define DIP   8512      // d_in_proj
#define CDIM  4352      // conv dim
#define BL    8192      // B_*L_

// ---------------- scratch (static device, allocation-free) ----------------
__device__ float g_zx [69730304];   // [BL][DIP]        zxbcdt
__device__ float g_xbc[35651584];   // [BL][CDIM]       conv+silu output
__device__ float g_dt [524288];     // [BL][NH]         softplus(dt)
__device__ float g_ac [524288];     // [b*NC][NH][CHK]  A_cum within chunk
__device__ float g_st [67108864];   // [b*NC][NH][HD][DST] states -> prev
__device__ float g_y  [33554432];   // [BL][DSSM]       y before gate/norm

// bf16 split operands for tensor-core GEMMs
__device__ __nv_bfloat16 g_uh [16777216], g_ul [16777216];   // u      [BL][DM]
__device__ __nv_bfloat16 g_w1h[17432576], g_w1l[17432576];   // W_in   [DIP][DM]
__device__ __nv_bfloat16 g_ynh[33554432], g_ynl[33554432];   // yn     [BL][DSSM]
__device__ __nv_bfloat16 g_w2h[ 8388608], g_w2l[ 8388608];   // W_out  [DM][DSSM]

// ---------------- helpers ----------------
__device__ __forceinline__ float siluf(float x) {
    return x / (1.f + __expf(-x));
}
__device__ __forceinline__ float softplusf(float x) {
    return x > 20.f ? x : log1pf(__expf(x));
}
__device__ __forceinline__ void split1(float x, __nv_bfloat16& h, __nv_bfloat16& l) {
    h = __float2bfloat16_rn(x);
    l = __float2bfloat16_rn(x - __bfloat162float(h));
}

// ---------------- cp.async / ldmatrix / mma helpers ----------------
__device__ __forceinline__ void cp16(uint32_t dst, const void* src) {
    asm volatile("cp.async.cg.shared.global [%0], [%1], 16;\n" :: "r"(dst), "l"(src));
}
__device__ __forceinline__ void cp16z(uint32_t dst, const void* src, int sz) {
    asm volatile("cp.async.cg.shared.global [%0], [%1], 16, %2;\n"
                 :: "r"(dst), "l"(src), "r"(sz));
}
#define CP_COMMIT() asm volatile("cp.async.commit_group;\n" ::: "memory")
#define CP_WAIT1()  asm volatile("cp.async.wait_group 1;\n" ::: "memory")
#define CP_WAIT0()  asm volatile("cp.async.wait_group 0;\n" ::: "memory")

__device__ __forceinline__ void ldsm4(uint32_t* r, uint32_t addr) {
    asm volatile("ldmatrix.sync.aligned.m8n8.x4.shared.b16 {%0,%1,%2,%3}, [%4];"
                 : "=r"(r[0]), "=r"(r[1]), "=r"(r[2]), "=r"(r[3]) : "r"(addr));
}
__device__ __forceinline__ void mma_bf16(float* c, const uint32_t* a, const uint32_t* b) {
    asm volatile(
        "mma.sync.aligned.m16n8k16.row.col.f32.bf16.bf16.f32 "
        "{%0,%1,%2,%3}, {%4,%5,%6,%7}, {%8,%9}, {%0,%1,%2,%3};\n"
        : "+f"(c[0]), "+f"(c[1]), "+f"(c[2]), "+f"(c[3])
        : "r"(a[0]), "r"(a[1]), "r"(a[2]), "r"(a[3]), "r"(b[0]), "r"(b[1]));
}

// ---------------- fp32 split kernel: x -> (hi, lo) bf16 ----------------
__global__ void split_kernel(const float* __restrict__ src,
                             __nv_bfloat16* __restrict__ h,
                             __nv_bfloat16* __restrict__ l, int n)
{
    int i = (blockIdx.x * blockDim.x + threadIdx.x) * 4;
    if (i >= n) return;
    float4 v = *(const float4*)(src + i);
    __nv_bfloat16 hh[4], ll[4];
    split1(v.x, hh[0], ll[0]); split1(v.y, hh[1], ll[1]);
    split1(v.z, hh[2], ll[2]); split1(v.w, hh[3], ll[3]);
    *(uint2*)(h + i) = *(uint2*)hh;
    *(uint2*)(l + i) = *(uint2*)ll;
}

// ---------------- bf16x3 mma.sync GEMM: C[M,Nn] = A[M,K]*B[Nn,K]^T ----------------
// A = Ah+Al, B = Bh+Bl (bf16 splits). C = AhBh + AhBl + AlBh (fp32 acc).
// 128x128 CTA tile, BK=32, 256 thr (8 warps, 4Mx2N, warp tile 32x64).
// Double-buffered cp.async. Product-outer MMA sweeps to break acc dependency chains.
#define BPITCH 80      // bytes per smem row (32 bf16 = 64B data + 16B pad)
#define MATB   10240   // bytes per 128-row matrix
#define STAGEB 40960   // 4 matrices per stage
#define GSMEM  81920   // 2 stages
__global__ void __launch_bounds__(256, 2) gemm_bf3(
    const __nv_bfloat16* __restrict__ Ah, const __nv_bfloat16* __restrict__ Al,
    const __nv_bfloat16* __restrict__ Bh, const __nv_bfloat16* __restrict__ Bl,
    float* __restrict__ C, int M, int Nn, int K, int tilesN, int group)
{
    extern __shared__ char smc[];
    uint32_t sb = (uint32_t)__cvta_generic_to_shared(smc);

    int tid = threadIdx.x;
    int wid = tid >> 5, lane = tid & 31;
    int wm = wid & 3, wn = wid >> 2;          // 4 x 2 warps
    int g = lane >> 2, kt = lane & 3;

    // grouped tile mapping for L2 reuse
    int tilesM = M >> 7;
    int pid = blockIdx.x;
    int gsize = group * tilesN;
    int gid = pid / gsize;
    int first = gid * group;
    int gsz = min(group, tilesM - first);
    int rem = pid - gid * gsize;
    int pm = first + rem % gsz;
    int pn = rem / gsz;
    int bm = pm << 7, bn = pn << 7;

    float acc[2][8][4];
    #pragma unroll
    for (int mt = 0; mt < 2; mt++)
        #pragma unroll
        for (int nt = 0; nt < 8; nt++)
            #pragma unroll
            for (int q = 0; q < 4; q++) acc[mt][nt][q] = 0.f;

    int niter = K >> 5;   // BK=32

    // stage loader: 4 matrices x 512 16B chunks = 8 per thread
    auto load_stage = [&](int st, int k0) {
        #pragma unroll
        for (int t = 0; t < 8; t++) {
            int mat = t >> 1;
            int idx = ((t & 1) << 8) + tid;      // 0..511
            int row = idx >> 2, c = idx & 3;
            uint32_t dst = sb + st * STAGEB + mat * MATB + row * BPITCH + c * 16;
            if (mat < 2) {
                const __nv_bfloat16* s =
                    (mat == 0 ? Ah : Al) + (size_t)(bm + row) * K + k0 + c * 8;
                cp16(dst, s);
            } else {
                int br = bn + row;
                int ok = (br < Nn) ? 16 : 0;
                const __nv_bfloat16* s =
                    (mat == 2 ? Bh : Bl) + (size_t)(ok ? br : 0) * K + k0 + c * 8;
                cp16z(dst, s, ok);
            }
        }
        CP_COMMIT();
    };

    load_stage(0, 0);

    int lrA = lane & 15, hcA = lane >> 4;
    int lrB = ((lane >> 4) << 3) + (lane & 7), hcB = (lane >> 3) & 1;

    for (int it = 0; it < niter; it++) {
        int buf = it & 1;
        if (it + 1 < niter) {
            load_stage(1 - buf, (it + 1) << 5);
            CP_WAIT1();
        } else {
            CP_WAIT0();
        }
        __syncthreads();

        uint32_t abase = sb + buf * STAGEB;
        #pragma unroll
        for (int ks = 0; ks < 2; ks++) {
            // load all fragments up front: B (shared across mt), then A (both mt)
            uint32_t bh[4][4], bl[4][4];
            #pragma unroll
            for (int p = 0; p < 4; p++) {
                uint32_t ad = abase + 2 * MATB +
                              (wn * 64 + p * 16 + lrB) * BPITCH + (ks * 2 + hcB) * 16;
                ldsm4(bh[p], ad);
                ldsm4(bl[p], ad + MATB);
            }
            uint32_t ah[2][4], al[2][4];
            #pragma unroll
            for (int mt = 0; mt < 2; mt++) {
                uint32_t ad = abase +
                              (wm * 32 + mt * 16 + lrA) * BPITCH + (ks * 2 + hcA) * 16;
                ldsm4(ah[mt], ad);
                ldsm4(al[mt], ad + MATB);
            }
            // product-outer sweeps: same-acc reuse distance = 16 MMAs
            #pragma unroll
            for (int mt = 0; mt < 2; mt++)
                #pragma unroll
                for (int nt = 0; nt < 8; nt++)
                    mma_bf16(acc[mt][nt], ah[mt], &bh[nt >> 1][(nt & 1) * 2]);
            #pragma unroll
            for (int mt = 0; mt < 2; mt++)
                #pragma unroll
                for (int nt = 0; nt < 8; nt++)
                    mma_bf16(acc[mt][nt], ah[mt], &bl[nt >> 1][(nt & 1) * 2]);
            #pragma unroll
            for (int mt = 0; mt < 2; mt++)
                #pragma unroll
                for (int nt = 0; nt < 8; nt++)
                    mma_bf16(acc[mt][nt], al[mt], &bh[nt >> 1][(nt & 1) * 2]);
        }
        __syncthreads();
    }

    // epilogue
    #pragma unroll
    for (int mt = 0; mt < 2; mt++) {
        int row = bm + wm * 32 + mt * 16 + g;
        #pragma unroll
        for (int nt = 0; nt < 8; nt++) {
            int col = bn + wn * 64 + nt * 8 + 2 * kt;
            if (col < Nn) {
                *(float2*)(C + (size_t)row * Nn + col) =
                    make_float2(acc[mt][nt][0], acc[mt][nt][1]);
                *(float2*)(C + (size_t)(row + 8) * Nn + col) =
                    make_float2(acc[mt][nt][2], acc[mt][nt][3]);
            }
        }
    }
}

// ---------------- causal depthwise conv (width 4) + bias + SiLU ----------------
// thread = one channel, 64 sequence positions (sliding window in regs)
__global__ void __launch_bounds__(256) conv_silu_kernel(
    const float* __restrict__ conv_w, const float* __restrict__ conv_b)
{
    int ch = blockIdx.x * 256 + threadIdx.x;
    if (ch >= CDIM) return;
    int lt = blockIdx.y;              // 0..127 tile of 64 positions
    int bl0 = lt * 64;                // global row base
    int l0 = bl0 & (L_ - 1);          // position within batch

    float w0 = conv_w[ch * 4 + 0], w1 = conv_w[ch * 4 + 1];
    float w2 = conv_w[ch * 4 + 2], w3 = conv_w[ch * 4 + 3];
    float bi = conv_b[ch];

    const float* src = g_zx + DSSM + ch;
    float x0 = (l0 >= 3) ? src[(size_t)(bl0 - 3) * DIP] : 0.f;
    float x1 = (l0 >= 2) ? src[(size_t)(bl0 - 2) * DIP] : 0.f;
    float x2 = (l0 >= 1) ? src[(size_t)(bl0 - 1) * DIP] : 0.f;

    float* dst = g_xbc + (size_t)bl0 * CDIM + ch;
    #pragma unroll 8
    for (int k = 0; k < 64; k++) {
        float x3 = src[(size_t)(bl0 + k) * DIP];
        float s = bi + w0 * x0 + w1 * x1 + w2 * x2 + w3 * x3;
        dst[(size_t)k * CDIM] = siluf(s);
        x0 = x1; x1 = x2; x2 = x3;
    }
}

// ---------------- dt = softplus(raw + bias) ----------------
__global__ void dt_kernel(const float* __restrict__ dt_bias)
{
    int idx = blockIdx.x * blockDim.x + threadIdx.x;
    if (idx >= BL * NH) return;
    int h  = idx & (NH - 1);
    int bl = idx >> 6;
    float x = g_zx[(size_t)bl * DIP + (DIP - NH) + h] + dt_bias[h];
    g_dt[idx] = softplusf(x);
}

// ---------------- per-chunk cumsum of dA = dt*A (batched loads) ----------------
__global__ void acum_kernel(const float* __restrict__ A_log)
{
    int bc = blockIdx.x;
    int h  = threadIdx.x;
    float A = -expf(A_log[h]);
    int rowbase = (bc >> 6) * L_ + (bc & (NC - 1)) * CHK;
    float v[64];
    #pragma unroll
    for (int l = 0; l < 64; l++)
        v[l] = g_dt[(size_t)(rowbase + l) * NH + h];
    float cum = 0.f;
    float* dst = g_ac + ((size_t)bc * NH + h) * CHK;
    #pragma unroll
    for (int l = 0; l < 64; l++) {
        cum += v[l] * A;
        dst[l] = cum;
    }
}

// ---------------- chunk kernel: CB, Y_diag (+D*x), chunk states ----------------
__global__ void __launch_bounds__(256) chunk_kernel(const float* __restrict__ Dv)
{
    extern __shared__ float smf[];
    float* Bs  = smf;              // [64][128]
    float* Cs  = Bs  + 64 * 128;   // [64][128]
    float* CB  = Cs  + 64 * 128;   // [64][64]
    float* xs  = CB  + 64 * 64;    // [64][64]
    float* Lw  = xs  + 64 * 64;    // [64][64]
    float* ac  = Lw  + 64 * 64;    // [64]
    float* dtl = ac  + 64;         // [64]
    float* vv  = dtl + 64;         // [64]

    int bc  = blockIdx.x;
    int tid = threadIdx.x;
    int rowbase = (bc >> 6) * L_ + (bc & (NC - 1)) * CHK;

    for (int i = tid; i < 64 * 32; i += 256) {
        int r  = i >> 5;
        int c4 = (i & 31) * 4;
        const float* rp = g_xbc + (size_t)(rowbase + r) * CDIM;
        *(float4*)&Bs[r * 128 + c4] = *(const float4*)(rp + DSSM + c4);
        *(float4*)&Cs[r * 128 + c4] = *(const float4*)(rp + DSSM + DST + c4);
    }
    __syncthreads();

    {
        int lt = (tid >> 4) * 4, st = (tid & 15) * 4;
        float acc[4][4];
        #pragma unroll
        for (int i = 0; i < 4; i++)
            #pragma unroll
            for (int j = 0; j < 4; j++) acc[i][j] = 0.f;
        for (int n = 0; n < 128; n++) {
            float a[4], b[4];
            #pragma unroll
            for (int i = 0; i < 4; i++) a[i] = Cs[(lt + i) * 128 + n];
            #pragma unroll
            for (int j = 0; j < 4; j++) b[j] = Bs[(st + j) * 128 + n];
            #pragma unroll
            for (int i = 0; i < 4; i++)
                #pragma unroll
                for (int j = 0; j < 4; j++) acc[i][j] += a[i] * b[j];
        }
        #pragma unroll
        for (int i = 0; i < 4; i++)
            #pragma unroll
            for (int j = 0; j < 4; j++) CB[(lt + i) * 64 + st + j] = acc[i][j];
    }
    __syncthreads();

    for (int h = 0; h < NH; h++) {
        for (int i = tid; i < 64 * 16; i += 256) {
            int r  = i >> 4;
            int c4 = (i & 15) * 4;
            *(float4*)&xs[r * 64 + c4] =
                *(const float4*)(g_xbc + (size_t)(rowbase + r) * CDIM + h * HD + c4);
        }
        if (tid < 64) {
            ac[tid]  = g_ac[((size_t)bc * NH + h) * CHK + tid];
            dtl[tid] = g_dt[(size_t)(rowbase + tid) * NH + h];
        }
        __syncthreads();
        if (tid < 64) vv[tid] = __expf(ac[63] - ac[tid]) * dtl[tid];
        for (int o = tid; o < 64 * 64; o += 256) {
            int l = o >> 6, s = o & 63;
            Lw[o] = (s <= l) ? CB[o] * __expf(ac[l] - ac[s]) * dtl[s] : 0.f;
        }
        __syncthreads();

        {
            int lt = (tid >> 4) * 4, pt = (tid & 15) * 4;
            float acc[4][4];
            #pragma unroll
            for (int i = 0; i < 4; i++)
                #pragma unroll
                for (int j = 0; j < 4; j++) acc[i][j] = 0.f;
            for (int s = 0; s < 64; s++) {
                float a[4], xb[4];
                #pragma unroll
                for (int i = 0; i < 4; i++) a[i] = Lw[(lt + i) * 64 + s];
                #pragma unroll
                for (int j = 0; j < 4; j++) xb[j] = xs[s * 64 + pt + j];
                #pragma unroll
                for (int i = 0; i < 4; i++)
                    #pragma unroll
                    for (int j = 0; j < 4; j++) acc[i][j] += a[i] * xb[j];
            }
            float Dh = Dv[h];
            #pragma unroll
            for (int i = 0; i < 4; i++) {
                int l = lt + i;
                size_t yrow = (size_t)(rowbase + l) * DSSM + h * HD;
                #pragma unroll
                for (int j = 0; j < 4; j++) {
                    int p = pt + j;
                    g_y[yrow + p] = acc[i][j] + Dh * xs[l * 64 + p];
                }
            }
        }

        {
            int pr = (tid >> 4) * 4, ncn = (tid & 15) * 8;
            float acc[4][8];
            #pragma unroll
            for (int i = 0; i < 4; i++)
                #pragma unroll
                for (int j = 0; j < 8; j++) acc[i][j] = 0.f;
            for (int l = 0; l < 64; l++) {
                float w = vv[l];
                float xv[4], bn[8];
                #pragma unroll
                for (int i = 0; i < 4; i++) xv[i] = xs[l * 64 + pr + i] * w;
                #pragma unroll
                for (int j = 0; j < 8; j++) bn[j] = Bs[l * 128 + ncn + j];
                #pragma unroll
                for (int i = 0; i < 4; i++)
                    #pragma unroll
                    for (int j = 0; j < 8; j++) acc[i][j] += xv[i] * bn[j];
            }
            size_t sbase = ((size_t)bc * NH + h) * (HD * DST);
            #pragma unroll
            for (int i = 0; i < 4; i++)
                #pragma unroll
                for (int j = 0; j < 8; j += 4)
                    *(float4*)&g_st[sbase + (size_t)(pr + i) * DST + ncn + j] =
                        make_float4(acc[i][j], acc[i][j+1], acc[i][j+2], acc[i][j+3]);
        }
        __syncthreads();
    }
}

// ---------------- inter-chunk scan (in-place: states -> prev) ----------------
__global__ void __launch_bounds__(256) scan_kernel()
{
    int b = blockIdx.x >> 6;
    int h = blockIdx.x & (NH - 1);
    int tid = threadIdx.x;
    float carry[32];
    #pragma unroll
    for (int k = 0; k < 32; k++) carry[k] = 0.f;

    for (int c = 0; c < NC; c++) {
        int bc = b * NC + c;
        float cd = __expf(g_ac[((size_t)bc * NH + h) * CHK + (CHK - 1)]);
        size_t base = ((size_t)bc * NH + h) * (HD * DST);
        #pragma unroll 4
        for (int k = 0; k < 32; k++) {
            size_t e = base + (size_t)k * 256 + tid;
            float s = g_st[e];
            g_st[e] = carry[k];
            carry[k] = carry[k] * cd + s;
        }
    }
}

// ---------------- Y_off: y += exp(Acum[l]) * (C[l] . prev[p]) ----------------
__global__ void __launch_bounds__(256) yoff_kernel()
{
    __shared__ float Ch[64 * 64];
    __shared__ float Ph[64 * 64];
    __shared__ float acs[64];

    int bc  = blockIdx.x;
    int h   = blockIdx.y;
    int tid = threadIdx.x;
    int rowbase = (bc >> 6) * L_ + (bc & (NC - 1)) * CHK;
    size_t sbase = ((size_t)bc * NH + h) * (HD * DST);

    if (tid < 64) acs[tid] = __expf(g_ac[((size_t)bc * NH + h) * CHK + tid]);

    int lt = (tid >> 4) * 4, pt = (tid & 15) * 4;
    float acc[4][4];
    #pragma unroll
    for (int i = 0; i < 4; i++)
        #pragma unroll
        for (int j = 0; j < 4; j++) acc[i][j] = 0.f;

    for (int half = 0; half < 2; half++) {
        __syncthreads();
        for (int i = tid; i < 64 * 16; i += 256) {
            int r  = i >> 4;
            int c4 = (i & 15) * 4;
            *(float4*)&Ch[r * 64 + c4] =
                *(const float4*)(g_xbc + (size_t)(rowbase + r) * CDIM + DSSM + DST + half * 64 + c4);
            *(float4*)&Ph[r * 64 + c4] =
                *(const float4*)(g_st + sbase + (size_t)r * DST + half * 64 + c4);
        }
        __syncthreads();
        for (int n = 0; n < 64; n++) {
            float a[4], p[4];
            #pragma unroll
            for (int i = 0; i < 4; i++) a[i] = Ch[(lt + i) * 64 + n];
            #pragma unroll
            for (int j = 0; j < 4; j++) p[j] = Ph[(pt + j) * 64 + n];
            #pragma unroll
            for (int i = 0; i < 4; i++)
                #pragma unroll
                for (int j = 0; j < 4; j++) acc[i][j] += a[i] * p[j];
        }
    }

    #pragma unroll
    for (int i = 0; i < 4; i++) {
        int l = lt + i;
        size_t yrow = (size_t)(rowbase + l) * DSSM + h * HD;
        float e = acs[l];
        #pragma unroll
        for (int j = 0; j < 4; j++)
            g_y[yrow + pt + j] += e * acc[i][j];
    }
}

// ---------------- gate (y * silu(z)) + RMSNorm -> bf16 split (ynh, ynl) ----------------
__global__ void __launch_bounds__(256) gatenorm_kernel(const float* __restrict__ nw)
{
    int row = blockIdx.x;
    int tid = threadIdx.x;
    float yg[16];
    float ss = 0.f;
    #pragma unroll
    for (int k = 0; k < 16; k++) {
        int i = k * 256 + tid;
        float y = g_y[(size_t)row * DSSM + i];
        float z = g_zx[(size_t)row * DIP + i];
        float v = y * siluf(z);
        yg[k] = v;
        ss += v * v;
    }
    __shared__ float red[256];
    red[tid] = ss;
    __syncthreads();
    for (int off = 128; off; off >>= 1) {
        if (tid < off) red[tid] += red[tid + off];
        __syncthreads();
    }
    float scale = rsqrtf(red[0] / (float)DSSM + 1e-5f);
    #pragma unroll
    for (int k = 0; k < 16; k++) {
        int i = k * 256 + tid;
        float t = yg[k] * scale * nw[i];
        __nv_bfloat16 h, l;
        split1(t, h, l);
        g_ynh[(size_t)row * DSSM + i] = h;
        g_ynl[(size_t)row * DSSM + i] = l;
    }
}

// ---------------- launch ----------------
extern "C" void kernel_launch(void* const* d_in, const int* in_sizes, int n_in,
                              void* d_out, int out_size)
{
    const float* u        = (const float*)d_in[0];
    const float* W_in     = (const float*)d_in[1];
    const float* conv_w   = (const float*)d_in[2];
    const float* conv_b   = (const float*)d_in[3];
    const float* dt_bias  = (const float*)d_in[4];
    const float* A_log    = (const float*)d_in[5];
    const float* Dv       = (const float*)d_in[6];
    const float* norm_w   = (const float*)d_in[7];
    const float* W_out    = (const float*)d_in[8];
    float* out = (float*)d_out;

    float* zx;
    cudaGetSymbolAddress((void**)&zx, g_zx);
    __nv_bfloat16 *uh, *ul, *w1h, *w1l, *ynh, *ynl, *w2h, *w2l;
    cudaGetSymbolAddress((void**)&uh,  g_uh);  cudaGetSymbolAddress((void**)&ul,  g_ul);
    cudaGetSymbolAddress((void**)&w1h, g_w1h); cudaGetSymbolAddress((void**)&w1l, g_w1l);
    cudaGetSymbolAddress((void**)&ynh, g_ynh); cudaGetSymbolAddress((void**)&ynl, g_ynl);
    cudaGetSymbolAddress((void**)&w2h, g_w2h); cudaGetSymbolAddress((void**)&w2l, g_w2l);

    const int CHUNK_SMEM = (64*128*2 + 64*64*3 + 64*3) * 4;  // 115456 B
    cudaFuncSetAttribute(chunk_kernel,
                         cudaFuncAttributeMaxDynamicSharedMemorySize, CHUNK_SMEM);
    cudaFuncSetAttribute(gemm_bf3,
                         cudaFuncAttributeMaxDynamicSharedMemorySize, GSMEM);

    // 0. split fp32 operands into bf16 (hi, lo)
    {
        int n1 = BL * DM;          // u
        int n2 = DIP * DM;         // W_in
        int n3 = DM * DSSM;        // W_out
        split_kernel<<<(n1 / 4 + 255) / 256, 256>>>(u, uh, ul, n1);
        split_kernel<<<(n2 / 4 + 255) / 256, 256>>>(W_in, w1h, w1l, n2);
        split_kernel<<<(n3 / 4 + 255) / 256, 256>>>(W_out, w2h, w2l, n3);
    }

    // 1. zxbcdt = u @ W_in^T   [8192 x 8512] via bf16x3 mma
    {
        int tilesM = BL / 128, tilesN = (DIP + 127) / 128;  // 64 x 67
        gemm_bf3<<<tilesM * tilesN, 256, GSMEM>>>(uh, ul, w1h, w1l, zx,
                                                  BL, DIP, DM, tilesN, 8);
    }
    // 2. conv + silu (sliding window)
    conv_silu_kernel<<<dim3((CDIM + 255) / 256, BL / 64), 256>>>(conv_w, conv_b);
    // 3. dt softplus
    dt_kernel<<<(BL * NH + 255) / 256, 256>>>(dt_bias);
    // 4. per-chunk A cumsum
    acum_kernel<<<B_ * NC, 64>>>(A_log);
    // 5. chunk-local: CB, Y_diag(+Dx), states
    chunk_kernel<<<B_ * NC, 256, CHUNK_SMEM>>>(Dv);
    // 6. inter-chunk scan
    scan_kernel<<<B_ * NH, 256>>>();
    // 7. Y_off accumulate
    yoff_kernel<<<dim3(B_ * NC, NH), 256>>>();
    // 8. gate + RMSNorm -> bf16 split
    gatenorm_kernel<<<BL, 256>>>(norm_w);
    // 9. out = yn @ W_out^T   [8192 x 2048] via bf16x3 mma
    {
        int tilesM = BL / 128, tilesN = DM / 128;  // 64 x 16
        gemm_bf3<<<tilesM * tilesN, 256, GSMEM>>>(ynh, ynl, w2h, w2l, out,
                                                  BL, DM, DSSM, tilesN, 8);
    }
}

// round 12
// speedup vs baseline: 1.4440x; 1.4440x over previous
#include <cuda_runtime.h>
#include <cuda_bf16.h>
#include <cstdint>

// ---------------- problem constants ----------------
#define B_    2
#define L_    4096
#define DM    2048      // d_model
#define DSSM  4096
#define DST   128       // d_state
#define NH    64        // heads
#define HD    64        // headdim
#define DCONV 4
#define CHK   64        // chunk length
#define NC    64        // num chunks (L/CHK)
#define DIP   8512      // d_in_proj
#define CDIM  4352      // conv dim
#define BL    8192      // B_*L_

// ---------------- scratch (static device, allocation-free) ----------------
__device__ float g_zx [69730304];   // [BL][DIP]        zxbcdt
__device__ float g_xbc[35651584];   // [BL][CDIM]       conv+silu output
__device__ float g_dt [524288];     // [BL][NH]         softplus(dt)
__device__ float g_ac [524288];     // [b*NC][NH][CHK]  A_cum within chunk
__device__ float g_st [67108864];   // [b*NC][NH][HD][DST] states -> prev
__device__ float g_y  [33554432];   // [BL][DSSM]       y before gate/norm

// bf16 split operands for tensor-core GEMMs
__device__ __nv_bfloat16 g_uh [16777216], g_ul [16777216];   // u      [BL][DM]
__device__ __nv_bfloat16 g_w1h[17432576], g_w1l[17432576];   // W_in   [DIP][DM]
__device__ __nv_bfloat16 g_ynh[33554432], g_ynl[33554432];   // yn     [BL][DSSM]
__device__ __nv_bfloat16 g_w2h[ 8388608], g_w2l[ 8388608];   // W_out  [DM][DSSM]

// ---------------- helpers ----------------
__device__ __forceinline__ float siluf(float x) {
    return x / (1.f + __expf(-x));
}
__device__ __forceinline__ float softplusf(float x) {
    return x > 20.f ? x : log1pf(__expf(x));
}
__device__ __forceinline__ void split1(float x, __nv_bfloat16& h, __nv_bfloat16& l) {
    h = __float2bfloat16_rn(x);
    l = __float2bfloat16_rn(x - __bfloat162float(h));
}

// ---------------- cp.async / ldmatrix / mma helpers ----------------
__device__ __forceinline__ void cp16(uint32_t dst, const void* src) {
    asm volatile("cp.async.cg.shared.global [%0], [%1], 16;\n" :: "r"(dst), "l"(src));
}
__device__ __forceinline__ void cp16z(uint32_t dst, const void* src, int sz) {
    asm volatile("cp.async.cg.shared.global [%0], [%1], 16, %2;\n"
                 :: "r"(dst), "l"(src), "r"(sz));
}
#define CP_COMMIT() asm volatile("cp.async.commit_group;\n" ::: "memory")
#define CP_WAIT1()  asm volatile("cp.async.wait_group 1;\n" ::: "memory")
#define CP_WAIT0()  asm volatile("cp.async.wait_group 0;\n" ::: "memory")

__device__ __forceinline__ void ldsm4(uint32_t* r, uint32_t addr) {
    asm volatile("ldmatrix.sync.aligned.m8n8.x4.shared.b16 {%0,%1,%2,%3}, [%4];"
                 : "=r"(r[0]), "=r"(r[1]), "=r"(r[2]), "=r"(r[3]) : "r"(addr));
}
__device__ __forceinline__ void mma_bf16(float* c, const uint32_t* a, const uint32_t* b) {
    asm volatile(
        "mma.sync.aligned.m16n8k16.row.col.f32.bf16.bf16.f32 "
        "{%0,%1,%2,%3}, {%4,%5,%6,%7}, {%8,%9}, {%0,%1,%2,%3};\n"
        : "+f"(c[0]), "+f"(c[1]), "+f"(c[2]), "+f"(c[3])
        : "r"(a[0]), "r"(a[1]), "r"(a[2]), "r"(a[3]), "r"(b[0]), "r"(b[1]));
}

// ---------------- fp32 split kernel: x -> (hi, lo) bf16 ----------------
__global__ void split_kernel(const float* __restrict__ src,
                             __nv_bfloat16* __restrict__ h,
                             __nv_bfloat16* __restrict__ l, int n)
{
    int i = (blockIdx.x * blockDim.x + threadIdx.x) * 4;
    if (i >= n) return;
    float4 v = *(const float4*)(src + i);
    __nv_bfloat16 hh[4], ll[4];
    split1(v.x, hh[0], ll[0]); split1(v.y, hh[1], ll[1]);
    split1(v.z, hh[2], ll[2]); split1(v.w, hh[3], ll[3]);
    *(uint2*)(h + i) = *(uint2*)hh;
    *(uint2*)(l + i) = *(uint2*)ll;
}

// ---------------- bf16x3 mma.sync GEMM: C[M,Nn] = A[M,K]*B[Nn,K]^T ----------------
// R6 measured-best configuration: BK=32, 2-stage, interleaved 3-product MMA,
// per-mt fragment loads (no hoisting -> no spills).
#define BPITCH 80      // bytes per smem row (32 bf16 = 64B data + 16B pad)
#define MATB   10240   // bytes per 128-row matrix
#define STAGEB 40960   // 4 matrices per stage
#define GSMEM  81920   // 2 stages
__global__ void __launch_bounds__(256, 2) gemm_bf3(
    const __nv_bfloat16* __restrict__ Ah, const __nv_bfloat16* __restrict__ Al,
    const __nv_bfloat16* __restrict__ Bh, const __nv_bfloat16* __restrict__ Bl,
    float* __restrict__ C, int M, int Nn, int K, int tilesN, int group)
{
    extern __shared__ char smc[];
    uint32_t sb = (uint32_t)__cvta_generic_to_shared(smc);

    int tid = threadIdx.x;
    int wid = tid >> 5, lane = tid & 31;
    int wm = wid & 3, wn = wid >> 2;          // 4 x 2 warps
    int g = lane >> 2, kt = lane & 3;

    // grouped tile mapping for L2 reuse
    int tilesM = M >> 7;
    int pid = blockIdx.x;
    int gsize = group * tilesN;
    int gid = pid / gsize;
    int first = gid * group;
    int gsz = min(group, tilesM - first);
    int rem = pid - gid * gsize;
    int pm = first + rem % gsz;
    int pn = rem / gsz;
    int bm = pm << 7, bn = pn << 7;

    float acc[2][8][4];
    #pragma unroll
    for (int mt = 0; mt < 2; mt++)
        #pragma unroll
        for (int nt = 0; nt < 8; nt++)
            #pragma unroll
            for (int q = 0; q < 4; q++) acc[mt][nt][q] = 0.f;

    int niter = K >> 5;   // BK=32

    // stage loader: 4 matrices x 512 16B chunks = 8 per thread
    auto load_stage = [&](int st, int k0) {
        #pragma unroll
        for (int t = 0; t < 8; t++) {
            int mat = t >> 1;
            int idx = ((t & 1) << 8) + tid;      // 0..511
            int row = idx >> 2, c = idx & 3;
            uint32_t dst = sb + st * STAGEB + mat * MATB + row * BPITCH + c * 16;
            if (mat < 2) {
                const __nv_bfloat16* s =
                    (mat == 0 ? Ah : Al) + (size_t)(bm + row) * K + k0 + c * 8;
                cp16(dst, s);
            } else {
                int br = bn + row;
                int ok = (br < Nn) ? 16 : 0;
                const __nv_bfloat16* s =
                    (mat == 2 ? Bh : Bl) + (size_t)(ok ? br : 0) * K + k0 + c * 8;
                cp16z(dst, s, ok);
            }
        }
        CP_COMMIT();
    };

    load_stage(0, 0);

    int lrA = lane & 15, hcA = lane >> 4;
    int lrB = ((lane >> 4) << 3) + (lane & 7), hcB = (lane >> 3) & 1;

    for (int it = 0; it < niter; it++) {
        int buf = it & 1;
        if (it + 1 < niter) {
            load_stage(1 - buf, (it + 1) << 5);
            CP_WAIT1();
        } else {
            CP_WAIT0();
        }
        __syncthreads();

        uint32_t abase = sb + buf * STAGEB;
        #pragma unroll
        for (int ks = 0; ks < 2; ks++) {
            uint32_t bh[4][4], bl[4][4];
            #pragma unroll
            for (int p = 0; p < 4; p++) {
                uint32_t ad = abase + 2 * MATB +
                              (wn * 64 + p * 16 + lrB) * BPITCH + (ks * 2 + hcB) * 16;
                ldsm4(bh[p], ad);
                ldsm4(bl[p], ad + MATB);
            }
            #pragma unroll
            for (int mt = 0; mt < 2; mt++) {
                uint32_t ad = abase +
                              (wm * 32 + mt * 16 + lrA) * BPITCH + (ks * 2 + hcA) * 16;
                uint32_t ah[4], al[4];
                ldsm4(ah, ad);
                ldsm4(al, ad + MATB);
                #pragma unroll
                for (int nt = 0; nt < 8; nt++) {
                    const uint32_t* fh = &bh[nt >> 1][(nt & 1) * 2];
                    const uint32_t* fl = &bl[nt >> 1][(nt & 1) * 2];
                    mma_bf16(acc[mt][nt], ah, fh);
                    mma_bf16(acc[mt][nt], ah, fl);
                    mma_bf16(acc[mt][nt], al, fh);
                }
            }
        }
        __syncthreads();
    }

    // epilogue
    #pragma unroll
    for (int mt = 0; mt < 2; mt++) {
        int row = bm + wm * 32 + mt * 16 + g;
        #pragma unroll
        for (int nt = 0; nt < 8; nt++) {
            int col = bn + wn * 64 + nt * 8 + 2 * kt;
            if (col < Nn) {
                *(float2*)(C + (size_t)row * Nn + col) =
                    make_float2(acc[mt][nt][0], acc[mt][nt][1]);
                *(float2*)(C + (size_t)(row + 8) * Nn + col) =
                    make_float2(acc[mt][nt][2], acc[mt][nt][3]);
            }
        }
    }
}

// ---------------- causal depthwise conv (width 4) + bias + SiLU ----------------
// thread = one channel, 64 sequence positions (sliding window in regs)
__global__ void __launch_bounds__(256) conv_silu_kernel(
    const float* __restrict__ conv_w, const float* __restrict__ conv_b)
{
    int ch = blockIdx.x * 256 + threadIdx.x;
    if (ch >= CDIM) return;
    int lt = blockIdx.y;              // 0..127 tile of 64 positions
    int bl0 = lt * 64;                // global row base
    int l0 = bl0 & (L_ - 1);          // position within batch

    float w0 = conv_w[ch * 4 + 0], w1 = conv_w[ch * 4 + 1];
    float w2 = conv_w[ch * 4 + 2], w3 = conv_w[ch * 4 + 3];
    float bi = conv_b[ch];

    const float* src = g_zx + DSSM + ch;
    float x0 = (l0 >= 3) ? src[(size_t)(bl0 - 3) * DIP] : 0.f;
    float x1 = (l0 >= 2) ? src[(size_t)(bl0 - 2) * DIP] : 0.f;
    float x2 = (l0 >= 1) ? src[(size_t)(bl0 - 1) * DIP] : 0.f;

    float* dst = g_xbc + (size_t)bl0 * CDIM + ch;
    #pragma unroll 8
    for (int k = 0; k < 64; k++) {
        float x3 = src[(size_t)(bl0 + k) * DIP];
        float s = bi + w0 * x0 + w1 * x1 + w2 * x2 + w3 * x3;
        dst[(size_t)k * CDIM] = siluf(s);
        x0 = x1; x1 = x2; x2 = x3;
    }
}

// ---------------- dt = softplus(raw + bias) ----------------
__global__ void dt_kernel(const float* __restrict__ dt_bias)
{
    int idx = blockIdx.x * blockDim.x + threadIdx.x;
    if (idx >= BL * NH) return;
    int h  = idx & (NH - 1);
    int bl = idx >> 6;
    float x = g_zx[(size_t)bl * DIP + (DIP - NH) + h] + dt_bias[h];
    g_dt[idx] = softplusf(x);
}

// ---------------- per-chunk cumsum of dA = dt*A (batched loads) ----------------
__global__ void acum_kernel(const float* __restrict__ A_log)
{
    int bc = blockIdx.x;
    int h  = threadIdx.x;
    float A = -expf(A_log[h]);
    int rowbase = (bc >> 6) * L_ + (bc & (NC - 1)) * CHK;
    float v[64];
    #pragma unroll
    for (int l = 0; l < 64; l++)
        v[l] = g_dt[(size_t)(rowbase + l) * NH + h];
    float cum = 0.f;
    float* dst = g_ac + ((size_t)bc * NH + h) * CHK;
    #pragma unroll
    for (int l = 0; l < 64; l++) {
        cum += v[l] * A;
        dst[l] = cum;
    }
}

// ---------------- chunk kernel: CB, Y_diag (+D*x), chunk states ----------------
// grid (128 chunks, 4 head-groups); each block does 16 heads. CB recomputed
// per group (cheap) -> 512 blocks, 2 CTAs/SM co-resident to hide gmem latency.
#define HGRP 4
#define HPB  (NH / HGRP)   // 16 heads per block
__global__ void __launch_bounds__(256) chunk_kernel(const float* __restrict__ Dv)
{
    extern __shared__ float smf[];
    float* Bs  = smf;              // [64][128]
    float* Cs  = Bs  + 64 * 128;   // [64][128]
    float* CB  = Cs  + 64 * 128;   // [64][64]
    float* xs  = CB  + 64 * 64;    // [64][64]
    float* Lw  = xs  + 64 * 64;    // [64][64]
    float* ac  = Lw  + 64 * 64;    // [64]
    float* dtl = ac  + 64;         // [64]
    float* vv  = dtl + 64;         // [64]

    int bc  = blockIdx.x;
    int h0  = blockIdx.y * HPB;
    int tid = threadIdx.x;
    int rowbase = (bc >> 6) * L_ + (bc & (NC - 1)) * CHK;

    for (int i = tid; i < 64 * 32; i += 256) {
        int r  = i >> 5;
        int c4 = (i & 31) * 4;
        const float* rp = g_xbc + (size_t)(rowbase + r) * CDIM;
        *(float4*)&Bs[r * 128 + c4] = *(const float4*)(rp + DSSM + c4);
        *(float4*)&Cs[r * 128 + c4] = *(const float4*)(rp + DSSM + DST + c4);
    }
    __syncthreads();

    {
        int lt = (tid >> 4) * 4, st = (tid & 15) * 4;
        float acc[4][4];
        #pragma unroll
        for (int i = 0; i < 4; i++)
            #pragma unroll
            for (int j = 0; j < 4; j++) acc[i][j] = 0.f;
        for (int n = 0; n < 128; n++) {
            float a[4], b[4];
            #pragma unroll
            for (int i = 0; i < 4; i++) a[i] = Cs[(lt + i) * 128 + n];
            #pragma unroll
            for (int j = 0; j < 4; j++) b[j] = Bs[(st + j) * 128 + n];
            #pragma unroll
            for (int i = 0; i < 4; i++)
                #pragma unroll
                for (int j = 0; j < 4; j++) acc[i][j] += a[i] * b[j];
        }
        #pragma unroll
        for (int i = 0; i < 4; i++)
            #pragma unroll
            for (int j = 0; j < 4; j++) CB[(lt + i) * 64 + st + j] = acc[i][j];
    }
    __syncthreads();

    for (int hh = 0; hh < HPB; hh++) {
        int h = h0 + hh;
        for (int i = tid; i < 64 * 16; i += 256) {
            int r  = i >> 4;
            int c4 = (i & 15) * 4;
            *(float4*)&xs[r * 64 + c4] =
                *(const float4*)(g_xbc + (size_t)(rowbase + r) * CDIM + h * HD + c4);
        }
        if (tid < 64) {
            ac[tid]  = g_ac[((size_t)bc * NH + h) * CHK + tid];
            dtl[tid] = g_dt[(size_t)(rowbase + tid) * NH + h];
        }
        __syncthreads();
        if (tid < 64) vv[tid] = __expf(ac[63] - ac[tid]) * dtl[tid];
        for (int o = tid; o < 64 * 64; o += 256) {
            int l = o >> 6, s = o & 63;
            Lw[o] = (s <= l) ? CB[o] * __expf(ac[l] - ac[s]) * dtl[s] : 0.f;
        }
        __syncthreads();

        {
            int lt = (tid >> 4) * 4, pt = (tid & 15) * 4;
            float acc[4][4];
            #pragma unroll
            for (int i = 0; i < 4; i++)
                #pragma unroll
                for (int j = 0; j < 4; j++) acc[i][j] = 0.f;
            for (int s = 0; s < 64; s++) {
                float a[4], xb[4];
                #pragma unroll
                for (int i = 0; i < 4; i++) a[i] = Lw[(lt + i) * 64 + s];
                #pragma unroll
                for (int j = 0; j < 4; j++) xb[j] = xs[s * 64 + pt + j];
                #pragma unroll
                for (int i = 0; i < 4; i++)
                    #pragma unroll
                    for (int j = 0; j < 4; j++) acc[i][j] += a[i] * xb[j];
            }
            float Dh = Dv[h];
            #pragma unroll
            for (int i = 0; i < 4; i++) {
                int l = lt + i;
                size_t yrow = (size_t)(rowbase + l) * DSSM + h * HD;
                #pragma unroll
                for (int j = 0; j < 4; j++) {
                    int p = pt + j;
                    g_y[yrow + p] = acc[i][j] + Dh * xs[l * 64 + p];
                }
            }
        }

        {
            int pr = (tid >> 4) * 4, ncn = (tid & 15) * 8;
            float acc[4][8];
            #pragma unroll
            for (int i = 0; i < 4; i++)
                #pragma unroll
                for (int j = 0; j < 8; j++) acc[i][j] = 0.f;
            for (int l = 0; l < 64; l++) {
                float w = vv[l];
                float xv[4], bn[8];
                #pragma unroll
                for (int i = 0; i < 4; i++) xv[i] = xs[l * 64 + pr + i] * w;
                #pragma unroll
                for (int j = 0; j < 8; j++) bn[j] = Bs[l * 128 + ncn + j];
                #pragma unroll
                for (int i = 0; i < 4; i++)
                    #pragma unroll
                    for (int j = 0; j < 8; j++) acc[i][j] += xv[i] * bn[j];
            }
            size_t sbase = ((size_t)bc * NH + h) * (HD * DST);
            #pragma unroll
            for (int i = 0; i < 4; i++)
                #pragma unroll
                for (int j = 0; j < 8; j += 4)
                    *(float4*)&g_st[sbase + (size_t)(pr + i) * DST + ncn + j] =
                        make_float4(acc[i][j], acc[i][j+1], acc[i][j+2], acc[i][j+3]);
        }
        __syncthreads();
    }
}

// ---------------- inter-chunk scan (in-place: states -> prev) ----------------
// grid (b*h, 4): each block owns 8 of the 32 k-slices -> 512 blocks
__global__ void __launch_bounds__(256) scan_kernel()
{
    int b = blockIdx.x >> 6;
    int h = blockIdx.x & (NH - 1);
    int k0 = blockIdx.y * 8;
    int tid = threadIdx.x;
    float carry[8];
    #pragma unroll
    for (int k = 0; k < 8; k++) carry[k] = 0.f;

    for (int c = 0; c < NC; c++) {
        int bc = b * NC + c;
        float cd = __expf(g_ac[((size_t)bc * NH + h) * CHK + (CHK - 1)]);
        size_t base = ((size_t)bc * NH + h) * (HD * DST) + (size_t)k0 * 256;
        #pragma unroll
        for (int k = 0; k < 8; k++) {
            size_t e = base + (size_t)k * 256 + tid;
            float s = g_st[e];
            g_st[e] = carry[k];
            carry[k] = carry[k] * cd + s;
        }
    }
}

// ---------------- Y_off: y += exp(Acum[l]) * (C[l] . prev[p]) ----------------
__global__ void __launch_bounds__(256) yoff_kernel()
{
    __shared__ float Ch[64 * 64];
    __shared__ float Ph[64 * 64];
    __shared__ float acs[64];

    int bc  = blockIdx.x;
    int h   = blockIdx.y;
    int tid = threadIdx.x;
    int rowbase = (bc >> 6) * L_ + (bc & (NC - 1)) * CHK;
    size_t sbase = ((size_t)bc * NH + h) * (HD * DST);

    if (tid < 64) acs[tid] = __expf(g_ac[((size_t)bc * NH + h) * CHK + tid]);

    int lt = (tid >> 4) * 4, pt = (tid & 15) * 4;
    float acc[4][4];
    #pragma unroll
    for (int i = 0; i < 4; i++)
        #pragma unroll
        for (int j = 0; j < 4; j++) acc[i][j] = 0.f;

    for (int half = 0; half < 2; half++) {
        __syncthreads();
        for (int i = tid; i < 64 * 16; i += 256) {
            int r  = i >> 4;
            int c4 = (i & 15) * 4;
            *(float4*)&Ch[r * 64 + c4] =
                *(const float4*)(g_xbc + (size_t)(rowbase + r) * CDIM + DSSM + DST + half * 64 + c4);
            *(float4*)&Ph[r * 64 + c4] =
                *(const float4*)(g_st + sbase + (size_t)r * DST + half * 64 + c4);
        }
        __syncthreads();
        for (int n = 0; n < 64; n++) {
            float a[4], p[4];
            #pragma unroll
            for (int i = 0; i < 4; i++) a[i] = Ch[(lt + i) * 64 + n];
            #pragma unroll
            for (int j = 0; j < 4; j++) p[j] = Ph[(pt + j) * 64 + n];
            #pragma unroll
            for (int i = 0; i < 4; i++)
                #pragma unroll
                for (int j = 0; j < 4; j++) acc[i][j] += a[i] * p[j];
        }
    }

    #pragma unroll
    for (int i = 0; i < 4; i++) {
        int l = lt + i;
        size_t yrow = (size_t)(rowbase + l) * DSSM + h * HD;
        float e = acs[l];
        #pragma unroll
        for (int j = 0; j < 4; j++)
            g_y[yrow + pt + j] += e * acc[i][j];
    }
}

// ---------------- gate (y * silu(z)) + RMSNorm -> bf16 split (ynh, ynl) ----------------
__global__ void __launch_bounds__(256) gatenorm_kernel(const float* __restrict__ nw)
{
    int row = blockIdx.x;
    int tid = threadIdx.x;
    float yg[16];
    float ss = 0.f;
    #pragma unroll
    for (int k = 0; k < 16; k++) {
        int i = k * 256 + tid;
        float y = g_y[(size_t)row * DSSM + i];
        float z = g_zx[(size_t)row * DIP + i];
        float v = y * siluf(z);
        yg[k] = v;
        ss += v * v;
    }
    __shared__ float red[256];
    red[tid] = ss;
    __syncthreads();
    for (int off = 128; off; off >>= 1) {
        if (tid < off) red[tid] += red[tid + off];
        __syncthreads();
    }
    float scale = rsqrtf(red[0] / (float)DSSM + 1e-5f);
    #pragma unroll
    for (int k = 0; k < 16; k++) {
        int i = k * 256 + tid;
        float t = yg[k] * scale * nw[i];
        __nv_bfloat16 h, l;
        split1(t, h, l);
        g_ynh[(size_t)row * DSSM + i] = h;
        g_ynl[(size_t)row * DSSM + i] = l;
    }
}

// ---------------- launch ----------------
extern "C" void kernel_launch(void* const* d_in, const int* in_sizes, int n_in,
                              void* d_out, int out_size)
{
    const float* u        = (const float*)d_in[0];
    const float* W_in     = (const float*)d_in[1];
    const float* conv_w   = (const float*)d_in[2];
    const float* conv_b   = (const float*)d_in[3];
    const float* dt_bias  = (const float*)d_in[4];
    const float* A_log    = (const float*)d_in[5];
    const float* Dv       = (const float*)d_in[6];
    const float* norm_w   = (const float*)d_in[7];
    const float* W_out    = (const float*)d_in[8];
    float* out = (float*)d_out;

    float* zx;
    cudaGetSymbolAddress((void**)&zx, g_zx);
    __nv_bfloat16 *uh, *ul, *w1h, *w1l, *ynh, *ynl, *w2h, *w2l;
    cudaGetSymbolAddress((void**)&uh,  g_uh);  cudaGetSymbolAddress((void**)&ul,  g_ul);
    cudaGetSymbolAddress((void**)&w1h, g_w1h); cudaGetSymbolAddress((void**)&w1l, g_w1l);
    cudaGetSymbolAddress((void**)&ynh, g_ynh); cudaGetSymbolAddress((void**)&ynl, g_ynl);
    cudaGetSymbolAddress((void**)&w2h, g_w2h); cudaGetSymbolAddress((void**)&w2l, g_w2l);

    const int CHUNK_SMEM = (64*128*2 + 64*64*3 + 64*3) * 4;  // 115456 B
    cudaFuncSetAttribute(chunk_kernel,
                         cudaFuncAttributeMaxDynamicSharedMemorySize, CHUNK_SMEM);
    cudaFuncSetAttribute(gemm_bf3,
                         cudaFuncAttributeMaxDynamicSharedMemorySize, GSMEM);

    // 0. split fp32 operands into bf16 (hi, lo)
    {
        int n1 = BL * DM;          // u
        int n2 = DIP * DM;         // W_in
        int n3 = DM * DSSM;        // W_out
        split_kernel<<<(n1 / 4 + 255) / 256, 256>>>(u, uh, ul, n1);
        split_kernel<<<(n2 / 4 + 255) / 256, 256>>>(W_in, w1h, w1l, n2);
        split_kernel<<<(n3 / 4 + 255) / 256, 256>>>(W_out, w2h, w2l, n3);
    }

    // 1. zxbcdt = u @ W_in^T   [8192 x 8512] via bf16x3 mma
    {
        int tilesM = BL / 128, tilesN = (DIP + 127) / 128;  // 64 x 67
        gemm_bf3<<<tilesM * tilesN, 256, GSMEM>>>(uh, ul, w1h, w1l, zx,
                                                  BL, DIP, DM, tilesN, 8);
    }
    // 2. conv + silu (sliding window)
    conv_silu_kernel<<<dim3((CDIM + 255) / 256, BL / 64), 256>>>(conv_w, conv_b);
    // 3. dt softplus
    dt_kernel<<<(BL * NH + 255) / 256, 256>>>(dt_bias);
    // 4. per-chunk A cumsum
    acum_kernel<<<B_ * NC, 64>>>(A_log);
    // 5. chunk-local: CB, Y_diag(+Dx), states  (4 head-groups)
    chunk_kernel<<<dim3(B_ * NC, HGRP), 256, CHUNK_SMEM>>>(Dv);
    // 6. inter-chunk scan (4 k-groups)
    scan_kernel<<<dim3(B_ * NH, 4), 256>>>();
    // 7. Y_off accumulate
    yoff_kernel<<<dim3(B_ * NC, NH), 256>>>();
    // 8. gate + RMSNorm -> bf16 split
    gatenorm_kernel<<<BL, 256>>>(norm_w);
    // 9. out = yn @ W_out^T   [8192 x 2048] via bf16x3 mma
    {
        int tilesM = BL / 128, tilesN = DM / 128;  // 64 x 16
        gemm_bf3<<<tilesM * tilesN, 256, GSMEM>>>(ynh, ynl, w2h, w2l, out,
                                                  BL, DM, DSSM, tilesN, 8);
    }
}

// round 13
// speedup vs baseline: 1.6052x; 1.1117x over previous
#include <cuda_runtime.h>
#include <cuda_bf16.h>
#include <cstdint>

// ---------------- problem constants ----------------
#define B_    2
#define L_    4096
#define DM    2048      // d_model
#define DSSM  4096
#define DST   128       // d_state
#define NH    64        // heads
#define HD    64        // headdim
#define DCONV 4
#define CHK   64        // chunk length
#define NC    64        // num chunks (L/CHK)
#define DIP   8512      // d_in_proj
#define CDIM  4352      // conv dim
#define BL    8192      // B_*L_

// ---------------- scratch (static device, allocation-free) ----------------
__device__ float g_zx [69730304];   // [BL][DIP]        zxbcdt
__device__ float g_xbc[35651584];   // [BL][CDIM]       conv+silu output
__device__ float g_dt [524288];     // [BL][NH]         softplus(dt)
__device__ float g_ac [524288];     // [b*NC][NH][CHK]  A_cum within chunk
__device__ float g_st [67108864];   // [b*NC][NH][HD][DST] states -> prev
__device__ float g_y  [33554432];   // [BL][DSSM]       y before gate/norm

// bf16 split operands for tensor-core GEMMs
__device__ __nv_bfloat16 g_uh [16777216], g_ul [16777216];   // u      [BL][DM]
__device__ __nv_bfloat16 g_w1h[17432576], g_w1l[17432576];   // W_in   [DIP][DM]
__device__ __nv_bfloat16 g_ynh[33554432], g_ynl[33554432];   // yn     [BL][DSSM]
__device__ __nv_bfloat16 g_w2h[ 8388608], g_w2l[ 8388608];   // W_out  [DM][DSSM]

// ---------------- helpers ----------------
__device__ __forceinline__ float siluf(float x) {
    return x / (1.f + __expf(-x));
}
__device__ __forceinline__ float softplusf(float x) {
    return x > 20.f ? x : log1pf(__expf(x));
}
__device__ __forceinline__ void split1(float x, __nv_bfloat16& h, __nv_bfloat16& l) {
    h = __float2bfloat16_rn(x);
    l = __float2bfloat16_rn(x - __bfloat162float(h));
}

// ---------------- cp.async / ldmatrix / mma helpers ----------------
__device__ __forceinline__ void cp16(uint32_t dst, const void* src) {
    asm volatile("cp.async.cg.shared.global [%0], [%1], 16;\n" :: "r"(dst), "l"(src));
}
__device__ __forceinline__ void cp16z(uint32_t dst, const void* src, int sz) {
    asm volatile("cp.async.cg.shared.global [%0], [%1], 16, %2;\n"
                 :: "r"(dst), "l"(src), "r"(sz));
}
#define CP_COMMIT() asm volatile("cp.async.commit_group;\n" ::: "memory")
#define CP_WAIT1()  asm volatile("cp.async.wait_group 1;\n" ::: "memory")
#define CP_WAIT0()  asm volatile("cp.async.wait_group 0;\n" ::: "memory")

__device__ __forceinline__ void ldsm4(uint32_t* r, uint32_t addr) {
    asm volatile("ldmatrix.sync.aligned.m8n8.x4.shared.b16 {%0,%1,%2,%3}, [%4];"
                 : "=r"(r[0]), "=r"(r[1]), "=r"(r[2]), "=r"(r[3]) : "r"(addr));
}
__device__ __forceinline__ void mma_bf16(float* c, const uint32_t* a, const uint32_t* b) {
    asm volatile(
        "mma.sync.aligned.m16n8k16.row.col.f32.bf16.bf16.f32 "
        "{%0,%1,%2,%3}, {%4,%5,%6,%7}, {%8,%9}, {%0,%1,%2,%3};\n"
        : "+f"(c[0]), "+f"(c[1]), "+f"(c[2]), "+f"(c[3])
        : "r"(a[0]), "r"(a[1]), "r"(a[2]), "r"(a[3]), "r"(b[0]), "r"(b[1]));
}

// ---------------- fp32 split kernel: x -> (hi, lo) bf16 ----------------
__global__ void split_kernel(const float* __restrict__ src,
                             __nv_bfloat16* __restrict__ h,
                             __nv_bfloat16* __restrict__ l, int n)
{
    int i = (blockIdx.x * blockDim.x + threadIdx.x) * 4;
    if (i >= n) return;
    float4 v = *(const float4*)(src + i);
    __nv_bfloat16 hh[4], ll[4];
    split1(v.x, hh[0], ll[0]); split1(v.y, hh[1], ll[1]);
    split1(v.z, hh[2], ll[2]); split1(v.w, hh[3], ll[3]);
    *(uint2*)(h + i) = *(uint2*)hh;
    *(uint2*)(l + i) = *(uint2*)ll;
}

// ---------------- bf16x3 mma.sync GEMM: C[M,Nn] = A[M,K]*B[Nn,K]^T ----------------
// 3-stage multistage pipeline, ONE __syncthreads per K-iter, XOR-swizzled smem
// (64B rows, slot = (chunk ^ (row>>1)) & 3 -> conflict-free ldmatrix + cp.async).
// BK=32, 256 thr (8 warps, 4Mx2N, warp tile 32x64), R6's measured-best MMA order.
#define MATB   8192    // bytes per 128-row matrix (128*64)
#define STAGEB 32768   // 4 matrices per stage
#define NSTG   3
#define GSMEM  98304   // 3 stages
__global__ void __launch_bounds__(256, 2) gemm_bf3(
    const __nv_bfloat16* __restrict__ Ah, const __nv_bfloat16* __restrict__ Al,
    const __nv_bfloat16* __restrict__ Bh, const __nv_bfloat16* __restrict__ Bl,
    float* __restrict__ C, int M, int Nn, int K, int tilesN, int group)
{
    extern __shared__ char smc[];
    uint32_t sb = (uint32_t)__cvta_generic_to_shared(smc);

    int tid = threadIdx.x;
    int wid = tid >> 5, lane = tid & 31;
    int wm = wid & 3, wn = wid >> 2;          // 4 x 2 warps
    int g = lane >> 2, kt = lane & 3;

    // grouped tile mapping for L2 reuse
    int tilesM = M >> 7;
    int pid = blockIdx.x;
    int gsize = group * tilesN;
    int gid = pid / gsize;
    int first = gid * group;
    int gsz = min(group, tilesM - first);
    int rem = pid - gid * gsize;
    int pm = first + rem % gsz;
    int pn = rem / gsz;
    int bm = pm << 7, bn = pn << 7;

    float acc[2][8][4];
    #pragma unroll
    for (int mt = 0; mt < 2; mt++)
        #pragma unroll
        for (int nt = 0; nt < 8; nt++)
            #pragma unroll
            for (int q = 0; q < 4; q++) acc[mt][nt][q] = 0.f;

    int niter = K >> 5;   // BK=32

    // stage loader: 4 matrices x 512 16B chunks = 8 per thread, XOR swizzle
    auto load_stage = [&](int st, int k0) {
        #pragma unroll
        for (int t = 0; t < 8; t++) {
            int mat = t >> 1;
            int idx = ((t & 1) << 8) + tid;      // 0..511
            int row = idx >> 2, c = idx & 3;
            uint32_t dst = sb + st * STAGEB + mat * MATB + row * 64
                         + (((c ^ (row >> 1)) & 3) << 4);
            if (mat < 2) {
                const __nv_bfloat16* s =
                    (mat == 0 ? Ah : Al) + (size_t)(bm + row) * K + k0 + c * 8;
                cp16(dst, s);
            } else {
                int br = bn + row;
                int ok = (br < Nn) ? 16 : 0;
                const __nv_bfloat16* s =
                    (mat == 2 ? Bh : Bl) + (size_t)(ok ? br : 0) * K + k0 + c * 8;
                cp16z(dst, s, ok);
            }
        }
        CP_COMMIT();
    };

    load_stage(0, 0);
    if (niter > 1) load_stage(1, 32);

    int lrA = lane & 15, hcA = lane >> 4;
    int lrB = ((lane >> 4) << 3) + (lane & 7), hcB = (lane >> 3) & 1;

    for (int it = 0; it < niter; it++) {
        if (it + 1 < niter) { CP_WAIT1(); } else { CP_WAIT0(); }
        __syncthreads();

        uint32_t abase = sb + (it % NSTG) * STAGEB;
        #pragma unroll
        for (int ks = 0; ks < 2; ks++) {
            uint32_t bh[4][4], bl[4][4];
            #pragma unroll
            for (int p = 0; p < 4; p++) {
                int rB = wn * 64 + p * 16 + lrB;
                uint32_t ad = abase + 2 * MATB + rB * 64
                            + ((((ks * 2 + hcB) ^ (rB >> 1)) & 3) << 4);
                ldsm4(bh[p], ad);
                ldsm4(bl[p], ad + MATB);
            }
            #pragma unroll
            for (int mt = 0; mt < 2; mt++) {
                int rA = wm * 32 + mt * 16 + lrA;
                uint32_t ad = abase + rA * 64
                            + ((((ks * 2 + hcA) ^ (rA >> 1)) & 3) << 4);
                uint32_t ah[4], al[4];
                ldsm4(ah, ad);
                ldsm4(al, ad + MATB);
                #pragma unroll
                for (int nt = 0; nt < 8; nt++) {
                    const uint32_t* fh = &bh[nt >> 1][(nt & 1) * 2];
                    const uint32_t* fl = &bl[nt >> 1][(nt & 1) * 2];
                    mma_bf16(acc[mt][nt], ah, fh);
                    mma_bf16(acc[mt][nt], ah, fl);
                    mma_bf16(acc[mt][nt], al, fh);
                }
            }
        }
        if (it + 2 < niter) load_stage((it + 2) % NSTG, (it + 2) << 5);
    }

    // epilogue
    #pragma unroll
    for (int mt = 0; mt < 2; mt++) {
        int row = bm + wm * 32 + mt * 16 + g;
        #pragma unroll
        for (int nt = 0; nt < 8; nt++) {
            int col = bn + wn * 64 + nt * 8 + 2 * kt;
            if (col < Nn) {
                *(float2*)(C + (size_t)row * Nn + col) =
                    make_float2(acc[mt][nt][0], acc[mt][nt][1]);
                *(float2*)(C + (size_t)(row + 8) * Nn + col) =
                    make_float2(acc[mt][nt][2], acc[mt][nt][3]);
            }
        }
    }
}

// ---------------- causal depthwise conv (width 4) + bias + SiLU ----------------
// thread = one channel, 64 sequence positions (sliding window in regs)
__global__ void __launch_bounds__(256) conv_silu_kernel(
    const float* __restrict__ conv_w, const float* __restrict__ conv_b)
{
    int ch = blockIdx.x * 256 + threadIdx.x;
    if (ch >= CDIM) return;
    int lt = blockIdx.y;              // 0..127 tile of 64 positions
    int bl0 = lt * 64;                // global row base
    int l0 = bl0 & (L_ - 1);          // position within batch

    float w0 = conv_w[ch * 4 + 0], w1 = conv_w[ch * 4 + 1];
    float w2 = conv_w[ch * 4 + 2], w3 = conv_w[ch * 4 + 3];
    float bi = conv_b[ch];

    const float* src = g_zx + DSSM + ch;
    float x0 = (l0 >= 3) ? src[(size_t)(bl0 - 3) * DIP] : 0.f;
    float x1 = (l0 >= 2) ? src[(size_t)(bl0 - 2) * DIP] : 0.f;
    float x2 = (l0 >= 1) ? src[(size_t)(bl0 - 1) * DIP] : 0.f;

    float* dst = g_xbc + (size_t)bl0 * CDIM + ch;
    #pragma unroll 8
    for (int k = 0; k < 64; k++) {
        float x3 = src[(size_t)(bl0 + k) * DIP];
        float s = bi + w0 * x0 + w1 * x1 + w2 * x2 + w3 * x3;
        dst[(size_t)k * CDIM] = siluf(s);
        x0 = x1; x1 = x2; x2 = x3;
    }
}

// ---------------- fused softplus(dt) + per-chunk cumsum of dA = dt*A ----------------
__global__ void acum_kernel(const float* __restrict__ A_log,
                            const float* __restrict__ dt_bias)
{
    int bc = blockIdx.x;
    int h  = threadIdx.x;
    float A = -expf(A_log[h]);
    float bias = dt_bias[h];
    int rowbase = (bc >> 6) * L_ + (bc & (NC - 1)) * CHK;
    float v[64];
    #pragma unroll
    for (int l = 0; l < 64; l++)
        v[l] = g_zx[(size_t)(rowbase + l) * DIP + (DIP - NH) + h] + bias;
    #pragma unroll
    for (int l = 0; l < 64; l++)
        v[l] = softplusf(v[l]);
    float cum = 0.f;
    float* dsta = g_ac + ((size_t)bc * NH + h) * CHK;
    #pragma unroll
    for (int l = 0; l < 64; l++) {
        g_dt[(size_t)(rowbase + l) * NH + h] = v[l];
        cum += v[l] * A;
        dsta[l] = cum;
    }
}

// ---------------- chunk kernel: CB, Y_diag (+D*x), chunk states ----------------
// grid (128 chunks, 4 head-groups); each block does 16 heads.
#define HGRP 4
#define HPB  (NH / HGRP)   // 16 heads per block
__global__ void __launch_bounds__(256) chunk_kernel(const float* __restrict__ Dv)
{
    extern __shared__ float smf[];
    float* Bs  = smf;              // [64][128]
    float* Cs  = Bs  + 64 * 128;   // [64][128]
    float* CB  = Cs  + 64 * 128;   // [64][64]
    float* xs  = CB  + 64 * 64;    // [64][64]
    float* Lw  = xs  + 64 * 64;    // [64][64]
    float* ac  = Lw  + 64 * 64;    // [64]
    float* dtl = ac  + 64;         // [64]
    float* vv  = dtl + 64;         // [64]

    int bc  = blockIdx.x;
    int h0  = blockIdx.y * HPB;
    int tid = threadIdx.x;
    int rowbase = (bc >> 6) * L_ + (bc & (NC - 1)) * CHK;

    for (int i = tid; i < 64 * 32; i += 256) {
        int r  = i >> 5;
        int c4 = (i & 31) * 4;
        const float* rp = g_xbc + (size_t)(rowbase + r) * CDIM;
        *(float4*)&Bs[r * 128 + c4] = *(const float4*)(rp + DSSM + c4);
        *(float4*)&Cs[r * 128 + c4] = *(const float4*)(rp + DSSM + DST + c4);
    }
    __syncthreads();

    {
        int lt = (tid >> 4) * 4, st = (tid & 15) * 4;
        float acc[4][4];
        #pragma unroll
        for (int i = 0; i < 4; i++)
            #pragma unroll
            for (int j = 0; j < 4; j++) acc[i][j] = 0.f;
        for (int n = 0; n < 128; n++) {
            float a[4], b[4];
            #pragma unroll
            for (int i = 0; i < 4; i++) a[i] = Cs[(lt + i) * 128 + n];
            #pragma unroll
            for (int j = 0; j < 4; j++) b[j] = Bs[(st + j) * 128 + n];
            #pragma unroll
            for (int i = 0; i < 4; i++)
                #pragma unroll
                for (int j = 0; j < 4; j++) acc[i][j] += a[i] * b[j];
        }
        #pragma unroll
        for (int i = 0; i < 4; i++)
            #pragma unroll
            for (int j = 0; j < 4; j++) CB[(lt + i) * 64 + st + j] = acc[i][j];
    }
    __syncthreads();

    for (int hh = 0; hh < HPB; hh++) {
        int h = h0 + hh;
        for (int i = tid; i < 64 * 16; i += 256) {
            int r  = i >> 4;
            int c4 = (i & 15) * 4;
            *(float4*)&xs[r * 64 + c4] =
                *(const float4*)(g_xbc + (size_t)(rowbase + r) * CDIM + h * HD + c4);
        }
        if (tid < 64) {
            ac[tid]  = g_ac[((size_t)bc * NH + h) * CHK + tid];
            dtl[tid] = g_dt[(size_t)(rowbase + tid) * NH + h];
        }
        __syncthreads();
        if (tid < 64) vv[tid] = __expf(ac[63] - ac[tid]) * dtl[tid];
        for (int o = tid; o < 64 * 64; o += 256) {
            int l = o >> 6, s = o & 63;
            Lw[o] = (s <= l) ? CB[o] * __expf(ac[l] - ac[s]) * dtl[s] : 0.f;
        }
        __syncthreads();

        {
            int lt = (tid >> 4) * 4, pt = (tid & 15) * 4;
            float acc[4][4];
            #pragma unroll
            for (int i = 0; i < 4; i++)
                #pragma unroll
                for (int j = 0; j < 4; j++) acc[i][j] = 0.f;
            for (int s = 0; s < 64; s++) {
                float a[4], xb[4];
                #pragma unroll
                for (int i = 0; i < 4; i++) a[i] = Lw[(lt + i) * 64 + s];
                #pragma unroll
                for (int j = 0; j < 4; j++) xb[j] = xs[s * 64 + pt + j];
                #pragma unroll
                for (int i = 0; i < 4; i++)
                    #pragma unroll
                    for (int j = 0; j < 4; j++) acc[i][j] += a[i] * xb[j];
            }
            float Dh = Dv[h];
            #pragma unroll
            for (int i = 0; i < 4; i++) {
                int l = lt + i;
                size_t yrow = (size_t)(rowbase + l) * DSSM + h * HD;
                #pragma unroll
                for (int j = 0; j < 4; j++) {
                    int p = pt + j;
                    g_y[yrow + p] = acc[i][j] + Dh * xs[l * 64 + p];
                }
            }
        }

        {
            int pr = (tid >> 4) * 4, ncn = (tid & 15) * 8;
            float acc[4][8];
            #pragma unroll
            for (int i = 0; i < 4; i++)
                #pragma unroll
                for (int j = 0; j < 8; j++) acc[i][j] = 0.f;
            for (int l = 0; l < 64; l++) {
                float w = vv[l];
                float xv[4], bn[8];
                #pragma unroll
                for (int i = 0; i < 4; i++) xv[i] = xs[l * 64 + pr + i] * w;
                #pragma unroll
                for (int j = 0; j < 8; j++) bn[j] = Bs[l * 128 + ncn + j];
                #pragma unroll
                for (int i = 0; i < 4; i++)
                    #pragma unroll
                    for (int j = 0; j < 8; j++) acc[i][j] += xv[i] * bn[j];
            }
            size_t sbase = ((size_t)bc * NH + h) * (HD * DST);
            #pragma unroll
            for (int i = 0; i < 4; i++)
                #pragma unroll
                for (int j = 0; j < 8; j += 4)
                    *(float4*)&g_st[sbase + (size_t)(pr + i) * DST + ncn + j] =
                        make_float4(acc[i][j], acc[i][j+1], acc[i][j+2], acc[i][j+3]);
        }
        __syncthreads();
    }
}

// ---------------- inter-chunk scan (in-place: states -> prev) ----------------
// grid (b*h, 4): each block owns 8 of the 32 k-slices
__global__ void __launch_bounds__(256) scan_kernel()
{
    int b = blockIdx.x >> 6;
    int h = blockIdx.x & (NH - 1);
    int k0 = blockIdx.y * 8;
    int tid = threadIdx.x;
    float carry[8];
    #pragma unroll
    for (int k = 0; k < 8; k++) carry[k] = 0.f;

    for (int c = 0; c < NC; c++) {
        int bc = b * NC + c;
        float cd = __expf(g_ac[((size_t)bc * NH + h) * CHK + (CHK - 1)]);
        size_t base = ((size_t)bc * NH + h) * (HD * DST) + (size_t)k0 * 256;
        #pragma unroll
        for (int k = 0; k < 8; k++) {
            size_t e = base + (size_t)k * 256 + tid;
            float s = g_st[e];
            g_st[e] = carry[k];
            carry[k] = carry[k] * cd + s;
        }
    }
}

// ---------------- Y_off: y += exp(Acum[l]) * (C[l] . prev[p]) ----------------
__global__ void __launch_bounds__(256) yoff_kernel()
{
    __shared__ float Ch[64 * 64];
    __shared__ float Ph[64 * 64];
    __shared__ float acs[64];

    int bc  = blockIdx.x;
    int h   = blockIdx.y;
    int tid = threadIdx.x;
    int rowbase = (bc >> 6) * L_ + (bc & (NC - 1)) * CHK;
    size_t sbase = ((size_t)bc * NH + h) * (HD * DST);

    if (tid < 64) acs[tid] = __expf(g_ac[((size_t)bc * NH + h) * CHK + tid]);

    int lt = (tid >> 4) * 4, pt = (tid & 15) * 4;
    float acc[4][4];
    #pragma unroll
    for (int i = 0; i < 4; i++)
        #pragma unroll
        for (int j = 0; j < 4; j++) acc[i][j] = 0.f;

    for (int half = 0; half < 2; half++) {
        __syncthreads();
        for (int i = tid; i < 64 * 16; i += 256) {
            int r  = i >> 4;
            int c4 = (i & 15) * 4;
            *(float4*)&Ch[r * 64 + c4] =
                *(const float4*)(g_xbc + (size_t)(rowbase + r) * CDIM + DSSM + DST + half * 64 + c4);
            *(float4*)&Ph[r * 64 + c4] =
                *(const float4*)(g_st + sbase + (size_t)r * DST + half * 64 + c4);
        }
        __syncthreads();
        for (int n = 0; n < 64; n++) {
            float a[4], p[4];
            #pragma unroll
            for (int i = 0; i < 4; i++) a[i] = Ch[(lt + i) * 64 + n];
            #pragma unroll
            for (int j = 0; j < 4; j++) p[j] = Ph[(pt + j) * 64 + n];
            #pragma unroll
            for (int i = 0; i < 4; i++)
                #pragma unroll
                for (int j = 0; j < 4; j++) acc[i][j] += a[i] * p[j];
        }
    }

    #pragma unroll
    for (int i = 0; i < 4; i++) {
        int l = lt + i;
        size_t yrow = (size_t)(rowbase + l) * DSSM + h * HD;
        float e = acs[l];
        #pragma unroll
        for (int j = 0; j < 4; j++)
            g_y[yrow + pt + j] += e * acc[i][j];
    }
}

// ---------------- gate (y * silu(z)) + RMSNorm -> bf16 split (ynh, ynl) ----------------
__global__ void __launch_bounds__(256) gatenorm_kernel(const float* __restrict__ nw)
{
    int row = blockIdx.x;
    int tid = threadIdx.x;
    float yg[16];
    float ss = 0.f;
    #pragma unroll
    for (int k = 0; k < 16; k++) {
        int i = k * 256 + tid;
        float y = g_y[(size_t)row * DSSM + i];
        float z = g_zx[(size_t)row * DIP + i];
        float v = y * siluf(z);
        yg[k] = v;
        ss += v * v;
    }
    __shared__ float red[256];
    red[tid] = ss;
    __syncthreads();
    for (int off = 128; off; off >>= 1) {
        if (tid < off) red[tid] += red[tid + off];
        __syncthreads();
    }
    float scale = rsqrtf(red[0] / (float)DSSM + 1e-5f);
    #pragma unroll
    for (int k = 0; k < 16; k++) {
        int i = k * 256 + tid;
        float t = yg[k] * scale * nw[i];
        __nv_bfloat16 h, l;
        split1(t, h, l);
        g_ynh[(size_t)row * DSSM + i] = h;
        g_ynl[(size_t)row * DSSM + i] = l;
    }
}

// ---------------- launch ----------------
extern "C" void kernel_launch(void* const* d_in, const int* in_sizes, int n_in,
                              void* d_out, int out_size)
{
    const float* u        = (const float*)d_in[0];
    const float* W_in     = (const float*)d_in[1];
    const float* conv_w   = (const float*)d_in[2];
    const float* conv_b   = (const float*)d_in[3];
    const float* dt_bias  = (const float*)d_in[4];
    const float* A_log    = (const float*)d_in[5];
    const float* Dv       = (const float*)d_in[6];
    const float* norm_w   = (const float*)d_in[7];
    const float* W_out    = (const float*)d_in[8];
    float* out = (float*)d_out;

    float* zx;
    cudaGetSymbolAddress((void**)&zx, g_zx);
    __nv_bfloat16 *uh, *ul, *w1h, *w1l, *ynh, *ynl, *w2h, *w2l;
    cudaGetSymbolAddress((void**)&uh,  g_uh);  cudaGetSymbolAddress((void**)&ul,  g_ul);
    cudaGetSymbolAddress((void**)&w1h, g_w1h); cudaGetSymbolAddress((void**)&w1l, g_w1l);
    cudaGetSymbolAddress((void**)&ynh, g_ynh); cudaGetSymbolAddress((void**)&ynl, g_ynl);
    cudaGetSymbolAddress((void**)&w2h, g_w2h); cudaGetSymbolAddress((void**)&w2l, g_w2l);

    const int CHUNK_SMEM = (64*128*2 + 64*64*3 + 64*3) * 4;  // 115456 B
    cudaFuncSetAttribute(chunk_kernel,
                         cudaFuncAttributeMaxDynamicSharedMemorySize, CHUNK_SMEM);
    cudaFuncSetAttribute(gemm_bf3,
                         cudaFuncAttributeMaxDynamicSharedMemorySize, GSMEM);

    // 0. split fp32 operands into bf16 (hi, lo)
    {
        int n1 = BL * DM;          // u
        int n2 = DIP * DM;         // W_in
        int n3 = DM * DSSM;        // W_out
        split_kernel<<<(n1 / 4 + 255) / 256, 256>>>(u, uh, ul, n1);
        split_kernel<<<(n2 / 4 + 255) / 256, 256>>>(W_in, w1h, w1l, n2);
        split_kernel<<<(n3 / 4 + 255) / 256, 256>>>(W_out, w2h, w2l, n3);
    }

    // 1. zxbcdt = u @ W_in^T   [8192 x 8512] via bf16x3 mma
    {
        int tilesM = BL / 128, tilesN = (DIP + 127) / 128;  // 64 x 67
        gemm_bf3<<<tilesM * tilesN, 256, GSMEM>>>(uh, ul, w1h, w1l, zx,
                                                  BL, DIP, DM, tilesN, 8);
    }
    // 2. conv + silu (sliding window)
    conv_silu_kernel<<<dim3((CDIM + 255) / 256, BL / 64), 256>>>(conv_w, conv_b);
    // 3+4. fused softplus(dt) + per-chunk A cumsum
    acum_kernel<<<B_ * NC, 64>>>(A_log, dt_bias);
    // 5. chunk-local: CB, Y_diag(+Dx), states  (4 head-groups)
    chunk_kernel<<<dim3(B_ * NC, HGRP), 256, CHUNK_SMEM>>>(Dv);
    // 6. inter-chunk scan (4 k-groups)
    scan_kernel<<<dim3(B_ * NH, 4), 256>>>();
    // 7. Y_off accumulate
    yoff_kernel<<<dim3(B_ * NC, NH), 256>>>();
    // 8. gate + RMSNorm -> bf16 split
    gatenorm_kernel<<<BL, 256>>>(norm_w);
    // 9. out = yn @ W_out^T   [8192 x 2048] via bf16x3 mma
    {
        int tilesM = BL / 128, tilesN = DM / 128;  // 64 x 16
        gemm_bf3<<<tilesM * tilesN, 256, GSMEM>>>(ynh, ynl, w2h, w2l, out,
                                                  BL, DM, DSSM, tilesN, 8);
    }
}

// round 14
// speedup vs baseline: 2.0691x; 1.2890x over previous
#include <cuda_runtime.h>
#include <cuda_bf16.h>
#include <cstdint>

// ---------------- problem constants ----------------
#define B_    2
#define L_    4096
#define DM    2048      // d_model
#define DSSM  4096
#define DST   128       // d_state
#define NH    64        // heads
#define HD    64        // headdim
#define DCONV 4
#define CHK   64        // chunk length
#define NC    64        // num chunks (L/CHK)
#define DIP   8512      // d_in_proj
#define CDIM  4352      // conv dim
#define BL    8192      // B_*L_

// ---------------- scratch (static device, allocation-free) ----------------
__device__ float g_zx [69730304];   // [BL][DIP]        zxbcdt
__device__ float g_xbc[35651584];   // [BL][CDIM]       conv+silu output
__device__ float g_dt [524288];     // [BL][NH]         softplus(dt)
__device__ float g_ac [524288];     // [b*NC][NH][CHK]  A_cum within chunk
__device__ float g_st [67108864];   // [b*NC][NH][HD][DST] states -> prev
__device__ float g_y  [33554432];   // [BL][DSSM]       y before gate/norm

// bf16 split operands for tensor-core GEMMs
__device__ __nv_bfloat16 g_uh [16777216], g_ul [16777216];   // u      [BL][DM]
__device__ __nv_bfloat16 g_w1h[17432576], g_w1l[17432576];   // W_in   [DIP][DM]
__device__ __nv_bfloat16 g_ynh[33554432], g_ynl[33554432];   // yn     [BL][DSSM]
__device__ __nv_bfloat16 g_w2h[ 8388608], g_w2l[ 8388608];   // W_out  [DM][DSSM]

// ---------------- helpers ----------------
__device__ __forceinline__ float siluf(float x) {
    return x / (1.f + __expf(-x));
}
__device__ __forceinline__ float softplusf(float x) {
    return x > 20.f ? x : log1pf(__expf(x));
}
__device__ __forceinline__ void split1(float x, __nv_bfloat16& h, __nv_bfloat16& l) {
    h = __float2bfloat16_rn(x);
    l = __float2bfloat16_rn(x - __bfloat162float(h));
}

// ---------------- cp.async / ldmatrix / mma helpers ----------------
__device__ __forceinline__ void cp16(uint32_t dst, const void* src) {
    asm volatile("cp.async.cg.shared.global [%0], [%1], 16;\n" :: "r"(dst), "l"(src));
}
__device__ __forceinline__ void cp16z(uint32_t dst, const void* src, int sz) {
    asm volatile("cp.async.cg.shared.global [%0], [%1], 16, %2;\n"
                 :: "r"(dst), "l"(src), "r"(sz));
}
#define CP_COMMIT() asm volatile("cp.async.commit_group;\n" ::: "memory")
#define CP_WAIT1()  asm volatile("cp.async.wait_group 1;\n" ::: "memory")
#define CP_WAIT0()  asm volatile("cp.async.wait_group 0;\n" ::: "memory")

__device__ __forceinline__ void ldsm4(uint32_t* r, uint32_t addr) {
    asm volatile("ldmatrix.sync.aligned.m8n8.x4.shared.b16 {%0,%1,%2,%3}, [%4];"
                 : "=r"(r[0]), "=r"(r[1]), "=r"(r[2]), "=r"(r[3]) : "r"(addr));
}
__device__ __forceinline__ void mma_bf16(float* c, const uint32_t* a, const uint32_t* b) {
    asm volatile(
        "mma.sync.aligned.m16n8k16.row.col.f32.bf16.bf16.f32 "
        "{%0,%1,%2,%3}, {%4,%5,%6,%7}, {%8,%9}, {%0,%1,%2,%3};\n"
        : "+f"(c[0]), "+f"(c[1]), "+f"(c[2]), "+f"(c[3])
        : "r"(a[0]), "r"(a[1]), "r"(a[2]), "r"(a[3]), "r"(b[0]), "r"(b[1]));
}

// ---------------- fp32 split kernel: x -> (hi, lo) bf16 ----------------
__global__ void split_kernel(const float* __restrict__ src,
                             __nv_bfloat16* __restrict__ h,
                             __nv_bfloat16* __restrict__ l, int n)
{
    int i = (blockIdx.x * blockDim.x + threadIdx.x) * 4;
    if (i >= n) return;
    float4 v = *(const float4*)(src + i);
    __nv_bfloat16 hh[4], ll[4];
    split1(v.x, hh[0], ll[0]); split1(v.y, hh[1], ll[1]);
    split1(v.z, hh[2], ll[2]); split1(v.w, hh[3], ll[3]);
    *(uint2*)(h + i) = *(uint2*)hh;
    *(uint2*)(l + i) = *(uint2*)ll;
}

// ---------------- bf16x3 mma.sync GEMM: C[M,Nn] = A[M,K]*B[Nn,K]^T ----------------
// R13 measured-best: 3-stage multistage, ONE sync/iter, XOR-swizzled smem.
#define MATB   8192    // bytes per 128-row matrix (128*64)
#define STAGEB 32768   // 4 matrices per stage
#define NSTG   3
#define GSMEM  98304   // 3 stages
__global__ void __launch_bounds__(256, 2) gemm_bf3(
    const __nv_bfloat16* __restrict__ Ah, const __nv_bfloat16* __restrict__ Al,
    const __nv_bfloat16* __restrict__ Bh, const __nv_bfloat16* __restrict__ Bl,
    float* __restrict__ C, int M, int Nn, int K, int tilesN, int group)
{
    extern __shared__ char smc[];
    uint32_t sb = (uint32_t)__cvta_generic_to_shared(smc);

    int tid = threadIdx.x;
    int wid = tid >> 5, lane = tid & 31;
    int wm = wid & 3, wn = wid >> 2;          // 4 x 2 warps
    int g = lane >> 2, kt = lane & 3;

    // grouped tile mapping for L2 reuse
    int tilesM = M >> 7;
    int pid = blockIdx.x;
    int gsize = group * tilesN;
    int gid = pid / gsize;
    int first = gid * group;
    int gsz = min(group, tilesM - first);
    int rem = pid - gid * gsize;
    int pm = first + rem % gsz;
    int pn = rem / gsz;
    int bm = pm << 7, bn = pn << 7;

    float acc[2][8][4];
    #pragma unroll
    for (int mt = 0; mt < 2; mt++)
        #pragma unroll
        for (int nt = 0; nt < 8; nt++)
            #pragma unroll
            for (int q = 0; q < 4; q++) acc[mt][nt][q] = 0.f;

    int niter = K >> 5;   // BK=32

    auto load_stage = [&](int st, int k0) {
        #pragma unroll
        for (int t = 0; t < 8; t++) {
            int mat = t >> 1;
            int idx = ((t & 1) << 8) + tid;      // 0..511
            int row = idx >> 2, c = idx & 3;
            uint32_t dst = sb + st * STAGEB + mat * MATB + row * 64
                         + (((c ^ (row >> 1)) & 3) << 4);
            if (mat < 2) {
                const __nv_bfloat16* s =
                    (mat == 0 ? Ah : Al) + (size_t)(bm + row) * K + k0 + c * 8;
                cp16(dst, s);
            } else {
                int br = bn + row;
                int ok = (br < Nn) ? 16 : 0;
                const __nv_bfloat16* s =
                    (mat == 2 ? Bh : Bl) + (size_t)(ok ? br : 0) * K + k0 + c * 8;
                cp16z(dst, s, ok);
            }
        }
        CP_COMMIT();
    };

    load_stage(0, 0);
    if (niter > 1) load_stage(1, 32);

    int lrA = lane & 15, hcA = lane >> 4;
    int lrB = ((lane >> 4) << 3) + (lane & 7), hcB = (lane >> 3) & 1;

    for (int it = 0; it < niter; it++) {
        if (it + 1 < niter) { CP_WAIT1(); } else { CP_WAIT0(); }
        __syncthreads();

        uint32_t abase = sb + (it % NSTG) * STAGEB;
        #pragma unroll
        for (int ks = 0; ks < 2; ks++) {
            uint32_t bh[4][4], bl[4][4];
            #pragma unroll
            for (int p = 0; p < 4; p++) {
                int rB = wn * 64 + p * 16 + lrB;
                uint32_t ad = abase + 2 * MATB + rB * 64
                            + ((((ks * 2 + hcB) ^ (rB >> 1)) & 3) << 4);
                ldsm4(bh[p], ad);
                ldsm4(bl[p], ad + MATB);
            }
            #pragma unroll
            for (int mt = 0; mt < 2; mt++) {
                int rA = wm * 32 + mt * 16 + lrA;
                uint32_t ad = abase + rA * 64
                            + ((((ks * 2 + hcA) ^ (rA >> 1)) & 3) << 4);
                uint32_t ah[4], al[4];
                ldsm4(ah, ad);
                ldsm4(al, ad + MATB);
                #pragma unroll
                for (int nt = 0; nt < 8; nt++) {
                    const uint32_t* fh = &bh[nt >> 1][(nt & 1) * 2];
                    const uint32_t* fl = &bl[nt >> 1][(nt & 1) * 2];
                    mma_bf16(acc[mt][nt], ah, fh);
                    mma_bf16(acc[mt][nt], ah, fl);
                    mma_bf16(acc[mt][nt], al, fh);
                }
            }
        }
        if (it + 2 < niter) load_stage((it + 2) % NSTG, (it + 2) << 5);
    }

    // epilogue
    #pragma unroll
    for (int mt = 0; mt < 2; mt++) {
        int row = bm + wm * 32 + mt * 16 + g;
        #pragma unroll
        for (int nt = 0; nt < 8; nt++) {
            int col = bn + wn * 64 + nt * 8 + 2 * kt;
            if (col < Nn) {
                *(float2*)(C + (size_t)row * Nn + col) =
                    make_float2(acc[mt][nt][0], acc[mt][nt][1]);
                *(float2*)(C + (size_t)(row + 8) * Nn + col) =
                    make_float2(acc[mt][nt][2], acc[mt][nt][3]);
            }
        }
    }
}

// ---------------- causal depthwise conv (width 4) + bias + SiLU ----------------
__global__ void __launch_bounds__(256) conv_silu_kernel(
    const float* __restrict__ conv_w, const float* __restrict__ conv_b)
{
    int ch = blockIdx.x * 256 + threadIdx.x;
    if (ch >= CDIM) return;
    int lt = blockIdx.y;
    int bl0 = lt * 64;
    int l0 = bl0 & (L_ - 1);

    float w0 = conv_w[ch * 4 + 0], w1 = conv_w[ch * 4 + 1];
    float w2 = conv_w[ch * 4 + 2], w3 = conv_w[ch * 4 + 3];
    float bi = conv_b[ch];

    const float* src = g_zx + DSSM + ch;
    float x0 = (l0 >= 3) ? src[(size_t)(bl0 - 3) * DIP] : 0.f;
    float x1 = (l0 >= 2) ? src[(size_t)(bl0 - 2) * DIP] : 0.f;
    float x2 = (l0 >= 1) ? src[(size_t)(bl0 - 1) * DIP] : 0.f;

    float* dst = g_xbc + (size_t)bl0 * CDIM + ch;
    #pragma unroll 8
    for (int k = 0; k < 64; k++) {
        float x3 = src[(size_t)(bl0 + k) * DIP];
        float s = bi + w0 * x0 + w1 * x1 + w2 * x2 + w3 * x3;
        dst[(size_t)k * CDIM] = siluf(s);
        x0 = x1; x1 = x2; x2 = x3;
    }
}

// ---------------- fused softplus(dt) + per-chunk cumsum of dA = dt*A ----------------
__global__ void acum_kernel(const float* __restrict__ A_log,
                            const float* __restrict__ dt_bias)
{
    int bc = blockIdx.x;
    int h  = threadIdx.x;
    float A = -expf(A_log[h]);
    float bias = dt_bias[h];
    int rowbase = (bc >> 6) * L_ + (bc & (NC - 1)) * CHK;
    float v[64];
    #pragma unroll
    for (int l = 0; l < 64; l++)
        v[l] = g_zx[(size_t)(rowbase + l) * DIP + (DIP - NH) + h] + bias;
    #pragma unroll
    for (int l = 0; l < 64; l++)
        v[l] = softplusf(v[l]);
    float cum = 0.f;
    float* dsta = g_ac + ((size_t)bc * NH + h) * CHK;
    #pragma unroll
    for (int l = 0; l < 64; l++) {
        g_dt[(size_t)(rowbase + l) * NH + h] = v[l];
        cum += v[l] * A;
        dsta[l] = cum;
    }
}

// ---------------- chunk kernel: CB, Y_diag (+D*x), chunk states ----------------
// Padded smem strides (129 / 65) kill bank conflicts; xs aliases Cs after CB.
// smem = (2*64*129 + 2*64*65 + 192) * 4 = 100096 B -> 2 CTAs/SM.
#define HGRP 4
#define HPB  (NH / HGRP)   // 16 heads per block
#define SP128 129
#define SP64  65
#define CHUNK_SMEM ((2*64*SP128 + 2*64*SP64 + 3*64) * 4)
__global__ void __launch_bounds__(256) chunk_kernel(const float* __restrict__ Dv)
{
    extern __shared__ float smf[];
    float* Bs  = smf;                    // [64][129]
    float* Cs  = Bs  + 64 * SP128;       // [64][129]  (reused as xs after CB)
    float* xs  = Cs;                     // alias [64][65]
    float* CB  = Cs  + 64 * SP128;       // [64][65]
    float* Lw  = CB  + 64 * SP64;        // [64][65]
    float* ac  = Lw  + 64 * SP64;        // [64]
    float* dtl = ac  + 64;               // [64]
    float* vv  = dtl + 64;               // [64]

    int bc  = blockIdx.x;
    int h0  = blockIdx.y * HPB;
    int tid = threadIdx.x;
    int rowbase = (bc >> 6) * L_ + (bc & (NC - 1)) * CHK;

    for (int i = tid; i < 64 * 32; i += 256) {
        int r  = i >> 5;
        int c4 = (i & 31) * 4;
        const float* rp = g_xbc + (size_t)(rowbase + r) * CDIM;
        float4 bv = *(const float4*)(rp + DSSM + c4);
        float4 cv = *(const float4*)(rp + DSSM + DST + c4);
        Bs[r * SP128 + c4 + 0] = bv.x; Bs[r * SP128 + c4 + 1] = bv.y;
        Bs[r * SP128 + c4 + 2] = bv.z; Bs[r * SP128 + c4 + 3] = bv.w;
        Cs[r * SP128 + c4 + 0] = cv.x; Cs[r * SP128 + c4 + 1] = cv.y;
        Cs[r * SP128 + c4 + 2] = cv.z; Cs[r * SP128 + c4 + 3] = cv.w;
    }
    __syncthreads();

    {
        int lt = (tid >> 4) * 4, st = (tid & 15) * 4;
        float acc[4][4];
        #pragma unroll
        for (int i = 0; i < 4; i++)
            #pragma unroll
            for (int j = 0; j < 4; j++) acc[i][j] = 0.f;
        for (int n = 0; n < 128; n++) {
            float a[4], b[4];
            #pragma unroll
            for (int i = 0; i < 4; i++) a[i] = Cs[(lt + i) * SP128 + n];
            #pragma unroll
            for (int j = 0; j < 4; j++) b[j] = Bs[(st + j) * SP128 + n];
            #pragma unroll
            for (int i = 0; i < 4; i++)
                #pragma unroll
                for (int j = 0; j < 4; j++) acc[i][j] += a[i] * b[j];
        }
        __syncthreads();   // CB write waits for all Cs reads (xs will alias Cs)
        #pragma unroll
        for (int i = 0; i < 4; i++)
            #pragma unroll
            for (int j = 0; j < 4; j++) CB[(lt + i) * SP64 + st + j] = acc[i][j];
    }
    __syncthreads();

    for (int hh = 0; hh < HPB; hh++) {
        int h = h0 + hh;
        for (int i = tid; i < 64 * 16; i += 256) {
            int r  = i >> 4;
            int c4 = (i & 15) * 4;
            float4 xv = *(const float4*)(g_xbc + (size_t)(rowbase + r) * CDIM + h * HD + c4);
            xs[r * SP64 + c4 + 0] = xv.x; xs[r * SP64 + c4 + 1] = xv.y;
            xs[r * SP64 + c4 + 2] = xv.z; xs[r * SP64 + c4 + 3] = xv.w;
        }
        if (tid < 64) {
            ac[tid]  = g_ac[((size_t)bc * NH + h) * CHK + tid];
            dtl[tid] = g_dt[(size_t)(rowbase + tid) * NH + h];
        }
        __syncthreads();
        if (tid < 64) vv[tid] = __expf(ac[63] - ac[tid]) * dtl[tid];
        for (int o = tid; o < 64 * 64; o += 256) {
            int l = o >> 6, s = o & 63;
            Lw[l * SP64 + s] = (s <= l) ? CB[l * SP64 + s] * __expf(ac[l] - ac[s]) * dtl[s] : 0.f;
        }
        __syncthreads();

        {
            int lt = (tid >> 4) * 4, pt = (tid & 15) * 4;
            float acc[4][4];
            #pragma unroll
            for (int i = 0; i < 4; i++)
                #pragma unroll
                for (int j = 0; j < 4; j++) acc[i][j] = 0.f;
            for (int s = 0; s < 64; s++) {
                float a[4], xb[4];
                #pragma unroll
                for (int i = 0; i < 4; i++) a[i] = Lw[(lt + i) * SP64 + s];
                #pragma unroll
                for (int j = 0; j < 4; j++) xb[j] = xs[s * SP64 + pt + j];
                #pragma unroll
                for (int i = 0; i < 4; i++)
                    #pragma unroll
                    for (int j = 0; j < 4; j++) acc[i][j] += a[i] * xb[j];
            }
            float Dh = Dv[h];
            #pragma unroll
            for (int i = 0; i < 4; i++) {
                int l = lt + i;
                size_t yrow = (size_t)(rowbase + l) * DSSM + h * HD;
                #pragma unroll
                for (int j = 0; j < 4; j++) {
                    int p = pt + j;
                    g_y[yrow + p] = acc[i][j] + Dh * xs[l * SP64 + p];
                }
            }
        }

        {
            int pr = (tid >> 4) * 4, ncn = (tid & 15) * 8;
            float acc[4][8];
            #pragma unroll
            for (int i = 0; i < 4; i++)
                #pragma unroll
                for (int j = 0; j < 8; j++) acc[i][j] = 0.f;
            for (int l = 0; l < 64; l++) {
                float w = vv[l];
                float xv[4], bn[8];
                #pragma unroll
                for (int i = 0; i < 4; i++) xv[i] = xs[l * SP64 + pr + i] * w;
                #pragma unroll
                for (int j = 0; j < 8; j++) bn[j] = Bs[l * SP128 + ncn + j];
                #pragma unroll
                for (int i = 0; i < 4; i++)
                    #pragma unroll
                    for (int j = 0; j < 8; j++) acc[i][j] += xv[i] * bn[j];
            }
            size_t sbase = ((size_t)bc * NH + h) * (HD * DST);
            #pragma unroll
            for (int i = 0; i < 4; i++)
                #pragma unroll
                for (int j = 0; j < 8; j += 4)
                    *(float4*)&g_st[sbase + (size_t)(pr + i) * DST + ncn + j] =
                        make_float4(acc[i][j], acc[i][j+1], acc[i][j+2], acc[i][j+3]);
        }
        __syncthreads();
    }
}

// ---------------- inter-chunk scan (in-place: states -> prev) ----------------
__global__ void __launch_bounds__(256) scan_kernel()
{
    int b = blockIdx.x >> 6;
    int h = blockIdx.x & (NH - 1);
    int k0 = blockIdx.y * 8;
    int tid = threadIdx.x;
    float carry[8];
    #pragma unroll
    for (int k = 0; k < 8; k++) carry[k] = 0.f;

    for (int c = 0; c < NC; c++) {
        int bc = b * NC + c;
        float cd = __expf(g_ac[((size_t)bc * NH + h) * CHK + (CHK - 1)]);
        size_t base = ((size_t)bc * NH + h) * (HD * DST) + (size_t)k0 * 256;
        #pragma unroll
        for (int k = 0; k < 8; k++) {
            size_t e = base + (size_t)k * 256 + tid;
            float s = g_st[e];
            g_st[e] = carry[k];
            carry[k] = carry[k] * cd + s;
        }
    }
}

// ---------------- Y_off: y += exp(Acum[l]) * (C[l] . prev[p]) ----------------
__global__ void __launch_bounds__(256) yoff_kernel()
{
    __shared__ float Ch[64 * SP64];
    __shared__ float Ph[64 * SP64];
    __shared__ float acs[64];

    int bc  = blockIdx.x;
    int h   = blockIdx.y;
    int tid = threadIdx.x;
    int rowbase = (bc >> 6) * L_ + (bc & (NC - 1)) * CHK;
    size_t sbase = ((size_t)bc * NH + h) * (HD * DST);

    if (tid < 64) acs[tid] = __expf(g_ac[((size_t)bc * NH + h) * CHK + tid]);

    int lt = (tid >> 4) * 4, pt = (tid & 15) * 4;
    float acc[4][4];
    #pragma unroll
    for (int i = 0; i < 4; i++)
        #pragma unroll
        for (int j = 0; j < 4; j++) acc[i][j] = 0.f;

    for (int half = 0; half < 2; half++) {
        __syncthreads();
        for (int i = tid; i < 64 * 16; i += 256) {
            int r  = i >> 4;
            int c4 = (i & 15) * 4;
            float4 cv = *(const float4*)(g_xbc + (size_t)(rowbase + r) * CDIM + DSSM + DST + half * 64 + c4);
            float4 pv = *(const float4*)(g_st + sbase + (size_t)r * DST + half * 64 + c4);
            Ch[r * SP64 + c4 + 0] = cv.x; Ch[r * SP64 + c4 + 1] = cv.y;
            Ch[r * SP64 + c4 + 2] = cv.z; Ch[r * SP64 + c4 + 3] = cv.w;
            Ph[r * SP64 + c4 + 0] = pv.x; Ph[r * SP64 + c4 + 1] = pv.y;
            Ph[r * SP64 + c4 + 2] = pv.z; Ph[r * SP64 + c4 + 3] = pv.w;
        }
        __syncthreads();
        for (int n = 0; n < 64; n++) {
            float a[4], p[4];
            #pragma unroll
            for (int i = 0; i < 4; i++) a[i] = Ch[(lt + i) * SP64 + n];
            #pragma unroll
            for (int j = 0; j < 4; j++) p[j] = Ph[(pt + j) * SP64 + n];
            #pragma unroll
            for (int i = 0; i < 4; i++)
                #pragma unroll
                for (int j = 0; j < 4; j++) acc[i][j] += a[i] * p[j];
        }
    }

    #pragma unroll
    for (int i = 0; i < 4; i++) {
        int l = lt + i;
        size_t yrow = (size_t)(rowbase + l) * DSSM + h * HD;
        float e = acs[l];
        #pragma unroll
        for (int j = 0; j < 4; j++)
            g_y[yrow + pt + j] += e * acc[i][j];
    }
}

// ---------------- gate (y * silu(z)) + RMSNorm -> bf16 split (ynh, ynl) ----------------
__global__ void __launch_bounds__(256) gatenorm_kernel(const float* __restrict__ nw)
{
    int row = blockIdx.x;
    int tid = threadIdx.x;
    float yg[16];
    float ss = 0.f;
    #pragma unroll
    for (int k = 0; k < 16; k++) {
        int i = k * 256 + tid;
        float y = g_y[(size_t)row * DSSM + i];
        float z = g_zx[(size_t)row * DIP + i];
        float v = y * siluf(z);
        yg[k] = v;
        ss += v * v;
    }
    __shared__ float red[256];
    red[tid] = ss;
    __syncthreads();
    for (int off = 128; off; off >>= 1) {
        if (tid < off) red[tid] += red[tid + off];
        __syncthreads();
    }
    float scale = rsqrtf(red[0] / (float)DSSM + 1e-5f);
    #pragma unroll
    for (int k = 0; k < 16; k++) {
        int i = k * 256 + tid;
        float t = yg[k] * scale * nw[i];
        __nv_bfloat16 h, l;
        split1(t, h, l);
        g_ynh[(size_t)row * DSSM + i] = h;
        g_ynl[(size_t)row * DSSM + i] = l;
    }
}

// ---------------- launch ----------------
extern "C" void kernel_launch(void* const* d_in, const int* in_sizes, int n_in,
                              void* d_out, int out_size)
{
    const float* u        = (const float*)d_in[0];
    const float* W_in     = (const float*)d_in[1];
    const float* conv_w   = (const float*)d_in[2];
    const float* conv_b   = (const float*)d_in[3];
    const float* dt_bias  = (const float*)d_in[4];
    const float* A_log    = (const float*)d_in[5];
    const float* Dv       = (const float*)d_in[6];
    const float* norm_w   = (const float*)d_in[7];
    const float* W_out    = (const float*)d_in[8];
    float* out = (float*)d_out;

    float* zx;
    cudaGetSymbolAddress((void**)&zx, g_zx);
    __nv_bfloat16 *uh, *ul, *w1h, *w1l, *ynh, *ynl, *w2h, *w2l;
    cudaGetSymbolAddress((void**)&uh,  g_uh);  cudaGetSymbolAddress((void**)&ul,  g_ul);
    cudaGetSymbolAddress((void**)&w1h, g_w1h); cudaGetSymbolAddress((void**)&w1l, g_w1l);
    cudaGetSymbolAddress((void**)&ynh, g_ynh); cudaGetSymbolAddress((void**)&ynl, g_ynl);
    cudaGetSymbolAddress((void**)&w2h, g_w2h); cudaGetSymbolAddress((void**)&w2l, g_w2l);

    cudaFuncSetAttribute(chunk_kernel,
                         cudaFuncAttributeMaxDynamicSharedMemorySize, CHUNK_SMEM);
    cudaFuncSetAttribute(gemm_bf3,
                         cudaFuncAttributeMaxDynamicSharedMemorySize, GSMEM);

    // 0. split fp32 operands into bf16 (hi, lo)
    {
        int n1 = BL * DM;          // u
        int n2 = DIP * DM;         // W_in
        int n3 = DM * DSSM;        // W_out
        split_kernel<<<(n1 / 4 + 255) / 256, 256>>>(u, uh, ul, n1);
        split_kernel<<<(n2 / 4 + 255) / 256, 256>>>(W_in, w1h, w1l, n2);
        split_kernel<<<(n3 / 4 + 255) / 256, 256>>>(W_out, w2h, w2l, n3);
    }

    // 1. zxbcdt = u @ W_in^T   [8192 x 8512] via bf16x3 mma
    {
        int tilesM = BL / 128, tilesN = (DIP + 127) / 128;  // 64 x 67
        gemm_bf3<<<tilesM * tilesN, 256, GSMEM>>>(uh, ul, w1h, w1l, zx,
                                                  BL, DIP, DM, tilesN, 8);
    }
    // 2. conv + silu (sliding window)
    conv_silu_kernel<<<dim3((CDIM + 255) / 256, BL / 64), 256>>>(conv_w, conv_b);
    // 3+4. fused softplus(dt) + per-chunk A cumsum
    acum_kernel<<<B_ * NC, 64>>>(A_log, dt_bias);
    // 5. chunk-local: CB, Y_diag(+Dx), states  (4 head-groups, 2 CTA/SM now)
    chunk_kernel<<<dim3(B_ * NC, HGRP), 256, CHUNK_SMEM>>>(Dv);
    // 6. inter-chunk scan (4 k-groups)
    scan_kernel<<<dim3(B_ * NH, 4), 256>>>();
    // 7. Y_off accumulate
    yoff_kernel<<<dim3(B_ * NC, NH), 256>>>();
    // 8. gate + RMSNorm -> bf16 split
    gatenorm_kernel<<<BL, 256>>>(norm_w);
    // 9. out = yn @ W_out^T   [8192 x 2048] via bf16x3 mma
    {
        int tilesM = BL / 128, tilesN = DM / 128;  // 64 x 16
        gemm_bf3<<<tilesM * tilesN, 256, GSMEM>>>(ynh, ynl, w2h, w2l, out,
                                                  BL, DM, DSSM, tilesN, 8);
    }
}

// round 15
// speedup vs baseline: 2.4928x; 1.2048x over previous
#include <cuda_runtime.h>
#include <cuda_fp16.h>
#include <cstdint>

// ---------------- problem constants ----------------
#define B_    2
#define L_    4096
#define DM    2048      // d_model
#define DSSM  4096
#define DST   128       // d_state
#define NH    64        // heads
#define HD    64        // headdim
#define DCONV 4
#define CHK   64        // chunk length
#define NC    64        // num chunks (L/CHK)
#define DIP   8512      // d_in_proj
#define CDIM  4352      // conv dim
#define BL    8192      // B_*L_

// ---------------- scratch (static device, allocation-free) ----------------
__device__ float g_zx [69730304];   // [BL][DIP]        zxbcdt
__device__ float g_xbc[35651584];   // [BL][CDIM]       conv+silu output
__device__ float g_dt [524288];     // [BL][NH]         softplus(dt)
__device__ float g_ac [524288];     // [b*NC][NH][CHK]  A_cum within chunk
__device__ float g_st [67108864];   // [b*NC][NH][HD][DST] states -> prev
__device__ float g_y  [33554432];   // [BL][DSSM]       y before gate/norm

// fp16 split operands for tensor-core GEMMs (A = h + l, B = h only)
__device__ __half g_uh [16777216], g_ul [16777216];   // u      [BL][DM]
__device__ __half g_w1h[17432576];                    // W_in   [DIP][DM]
__device__ __half g_ynh[33554432], g_ynl[33554432];   // yn     [BL][DSSM]
__device__ __half g_w2h[ 8388608];                    // W_out  [DM][DSSM]

// ---------------- helpers ----------------
__device__ __forceinline__ float siluf(float x) {
    return x / (1.f + __expf(-x));
}
__device__ __forceinline__ float softplusf(float x) {
    return x > 20.f ? x : log1pf(__expf(x));
}
__device__ __forceinline__ void split1(float x, __half& h, __half& l) {
    h = __float2half_rn(x);
    l = __float2half_rn(x - __half2float(h));
}

// ---------------- cp.async / ldmatrix / mma helpers ----------------
__device__ __forceinline__ void cp16(uint32_t dst, const void* src) {
    asm volatile("cp.async.cg.shared.global [%0], [%1], 16;\n" :: "r"(dst), "l"(src));
}
__device__ __forceinline__ void cp16z(uint32_t dst, const void* src, int sz) {
    asm volatile("cp.async.cg.shared.global [%0], [%1], 16, %2;\n"
                 :: "r"(dst), "l"(src), "r"(sz));
}
#define CP_COMMIT() asm volatile("cp.async.commit_group;\n" ::: "memory")
#define CP_WAIT2()  asm volatile("cp.async.wait_group 2;\n" ::: "memory")
#define CP_WAIT0()  asm volatile("cp.async.wait_group 0;\n" ::: "memory")

__device__ __forceinline__ void ldsm4(uint32_t* r, uint32_t addr) {
    asm volatile("ldmatrix.sync.aligned.m8n8.x4.shared.b16 {%0,%1,%2,%3}, [%4];"
                 : "=r"(r[0]), "=r"(r[1]), "=r"(r[2]), "=r"(r[3]) : "r"(addr));
}
__device__ __forceinline__ void mma_fp16(float* c, const uint32_t* a, const uint32_t* b) {
    asm volatile(
        "mma.sync.aligned.m16n8k16.row.col.f32.f16.f16.f32 "
        "{%0,%1,%2,%3}, {%4,%5,%6,%7}, {%8,%9}, {%0,%1,%2,%3};\n"
        : "+f"(c[0]), "+f"(c[1]), "+f"(c[2]), "+f"(c[3])
        : "r"(a[0]), "r"(a[1]), "r"(a[2]), "r"(a[3]), "r"(b[0]), "r"(b[1]));
}

// ---------------- fp32 -> fp16 (hi, lo) split ----------------
__global__ void split2_kernel(const float* __restrict__ src,
                              __half* __restrict__ h,
                              __half* __restrict__ l, int n)
{
    int i = (blockIdx.x * blockDim.x + threadIdx.x) * 4;
    if (i >= n) return;
    float4 v = *(const float4*)(src + i);
    __half hh[4], ll[4];
    split1(v.x, hh[0], ll[0]); split1(v.y, hh[1], ll[1]);
    split1(v.z, hh[2], ll[2]); split1(v.w, hh[3], ll[3]);
    *(uint2*)(h + i) = *(uint2*)hh;
    *(uint2*)(l + i) = *(uint2*)ll;
}

// ---------------- fp32 -> fp16 (hi only) ----------------
__global__ void splith_kernel(const float* __restrict__ src,
                              __half* __restrict__ h, int n)
{
    int i = (blockIdx.x * blockDim.x + threadIdx.x) * 4;
    if (i >= n) return;
    float4 v = *(const float4*)(src + i);
    __half hh[4];
    hh[0] = __float2half_rn(v.x); hh[1] = __float2half_rn(v.y);
    hh[2] = __float2half_rn(v.z); hh[3] = __float2half_rn(v.w);
    *(uint2*)(h + i) = *(uint2*)hh;
}

// ---------------- fp16x2 mma.sync GEMM: C[M,Nn] = (Ah+Al)[M,K] * Bh[Nn,K]^T --------
// 4-stage multistage (depth-2 prefetch), ONE __syncthreads per K-iter,
// XOR-swizzled smem (64B rows). BK=32, 256 thr (8 warps 4Mx2N, warp tile 32x64).
// 2 MMAs per (mt,nt) per k16: Ah*Bh + Al*Bh.
#define MATB   8192    // bytes per 128-row matrix (128*64)
#define STAGEB 24576   // 3 matrices per stage (Ah, Al, Bh)
#define NSTG   4
#define GSMEM  98304   // 4 stages
__global__ void __launch_bounds__(256, 2) gemm_fp16x2(
    const __half* __restrict__ Ah, const __half* __restrict__ Al,
    const __half* __restrict__ Bh,
    float* __restrict__ C, int M, int Nn, int K, int tilesN, int group)
{
    extern __shared__ char smc[];
    uint32_t sb = (uint32_t)__cvta_generic_to_shared(smc);

    int tid = threadIdx.x;
    int wid = tid >> 5, lane = tid & 31;
    int wm = wid & 3, wn = wid >> 2;          // 4 x 2 warps
    int g = lane >> 2, kt = lane & 3;

    // grouped tile mapping for L2 reuse
    int tilesM = M >> 7;
    int pid = blockIdx.x;
    int gsize = group * tilesN;
    int gid = pid / gsize;
    int first = gid * group;
    int gsz = min(group, tilesM - first);
    int rem = pid - gid * gsize;
    int pm = first + rem % gsz;
    int pn = rem / gsz;
    int bm = pm << 7, bn = pn << 7;

    float acc[2][8][4];
    #pragma unroll
    for (int mt = 0; mt < 2; mt++)
        #pragma unroll
        for (int nt = 0; nt < 8; nt++)
            #pragma unroll
            for (int q = 0; q < 4; q++) acc[mt][nt][q] = 0.f;

    int niter = K >> 5;   // BK=32

    // stage loader: 3 matrices x 512 16B chunks = 6 per thread, XOR swizzle
    auto load_stage = [&](int st, int k0) {
        #pragma unroll
        for (int t = 0; t < 6; t++) {
            int mat = t >> 1;                    // 0:Ah 1:Al 2:Bh
            int idx = ((t & 1) << 8) + tid;      // 0..511
            int row = idx >> 2, c = idx & 3;
            uint32_t dst = sb + st * STAGEB + mat * MATB + row * 64
                         + (((c ^ (row >> 1)) & 3) << 4);
            if (mat < 2) {
                const __half* s =
                    (mat == 0 ? Ah : Al) + (size_t)(bm + row) * K + k0 + c * 8;
                cp16(dst, s);
            } else {
                int br = bn + row;
                int ok = (br < Nn) ? 16 : 0;
                const __half* s = Bh + (size_t)(ok ? br : 0) * K + k0 + c * 8;
                cp16z(dst, s, ok);
            }
        }
        CP_COMMIT();
    };

    load_stage(0, 0);
    load_stage(1, 32);
    load_stage(2, 64);

    int lrA = lane & 15, hcA = lane >> 4;
    int lrB = ((lane >> 4) << 3) + (lane & 7), hcB = (lane >> 3) & 1;

    for (int it = 0; it < niter; it++) {
        if (it + 1 < niter) { CP_WAIT2(); } else { CP_WAIT0(); }
        __syncthreads();

        uint32_t abase = sb + (it & (NSTG - 1)) * STAGEB;

        // ks = 0
        {
            uint32_t bh[4][4];
            #pragma unroll
            for (int p = 0; p < 4; p++) {
                int rB = wn * 64 + p * 16 + lrB;
                ldsm4(bh[p], abase + 2 * MATB + rB * 64
                             + (((hcB ^ (rB >> 1)) & 3) << 4));
            }
            #pragma unroll
            for (int mt = 0; mt < 2; mt++) {
                int rA = wm * 32 + mt * 16 + lrA;
                uint32_t ad = abase + rA * 64 + (((hcA ^ (rA >> 1)) & 3) << 4);
                uint32_t ah[4], al[4];
                ldsm4(ah, ad);
                ldsm4(al, ad + MATB);
                #pragma unroll
                for (int nt = 0; nt < 8; nt++) {
                    const uint32_t* fh = &bh[nt >> 1][(nt & 1) * 2];
                    mma_fp16(acc[mt][nt], ah, fh);
                    mma_fp16(acc[mt][nt], al, fh);
                }
            }
        }

        // issue next stage's loads here so the LSU burst hides under ks=1 MMAs
        if (it + 3 < niter) load_stage((it + 3) & (NSTG - 1), (it + 3) << 5);
        else CP_COMMIT();   // empty group keeps wait_group accounting correct

        // ks = 1
        {
            uint32_t bh[4][4];
            #pragma unroll
            for (int p = 0; p < 4; p++) {
                int rB = wn * 64 + p * 16 + lrB;
                ldsm4(bh[p], abase + 2 * MATB + rB * 64
                             + ((((2 + hcB) ^ (rB >> 1)) & 3) << 4));
            }
            #pragma unroll
            for (int mt = 0; mt < 2; mt++) {
                int rA = wm * 32 + mt * 16 + lrA;
                uint32_t ad = abase + rA * 64
                            + ((((2 + hcA) ^ (rA >> 1)) & 3) << 4);
                uint32_t ah[4], al[4];
                ldsm4(ah, ad);
                ldsm4(al, ad + MATB);
                #pragma unroll
                for (int nt = 0; nt < 8; nt++) {
                    const uint32_t* fh = &bh[nt >> 1][(nt & 1) * 2];
                    mma_fp16(acc[mt][nt], ah, fh);
                    mma_fp16(acc[mt][nt], al, fh);
                }
            }
        }
    }

    // epilogue
    #pragma unroll
    for (int mt = 0; mt < 2; mt++) {
        int row = bm + wm * 32 + mt * 16 + g;
        #pragma unroll
        for (int nt = 0; nt < 8; nt++) {
            int col = bn + wn * 64 + nt * 8 + 2 * kt;
            if (col < Nn) {
                *(float2*)(C + (size_t)row * Nn + col) =
                    make_float2(acc[mt][nt][0], acc[mt][nt][1]);
                *(float2*)(C + (size_t)(row + 8) * Nn + col) =
                    make_float2(acc[mt][nt][2], acc[mt][nt][3]);
            }
        }
    }
}

// ---------------- causal depthwise conv (width 4) + bias + SiLU ----------------
__global__ void __launch_bounds__(256) conv_silu_kernel(
    const float* __restrict__ conv_w, const float* __restrict__ conv_b)
{
    int ch = blockIdx.x * 256 + threadIdx.x;
    if (ch >= CDIM) return;
    int lt = blockIdx.y;
    int bl0 = lt * 64;
    int l0 = bl0 & (L_ - 1);

    float w0 = conv_w[ch * 4 + 0], w1 = conv_w[ch * 4 + 1];
    float w2 = conv_w[ch * 4 + 2], w3 = conv_w[ch * 4 + 3];
    float bi = conv_b[ch];

    const float* src = g_zx + DSSM + ch;
    float x0 = (l0 >= 3) ? src[(size_t)(bl0 - 3) * DIP] : 0.f;
    float x1 = (l0 >= 2) ? src[(size_t)(bl0 - 2) * DIP] : 0.f;
    float x2 = (l0 >= 1) ? src[(size_t)(bl0 - 1) * DIP] : 0.f;

    float* dst = g_xbc + (size_t)bl0 * CDIM + ch;
    #pragma unroll 8
    for (int k = 0; k < 64; k++) {
        float x3 = src[(size_t)(bl0 + k) * DIP];
        float s = bi + w0 * x0 + w1 * x1 + w2 * x2 + w3 * x3;
        dst[(size_t)k * CDIM] = siluf(s);
        x0 = x1; x1 = x2; x2 = x3;
    }
}

// ---------------- fused softplus(dt) + per-chunk cumsum of dA = dt*A ----------------
__global__ void acum_kernel(const float* __restrict__ A_log,
                            const float* __restrict__ dt_bias)
{
    int bc = blockIdx.x;
    int h  = threadIdx.x;
    float A = -expf(A_log[h]);
    float bias = dt_bias[h];
    int rowbase = (bc >> 6) * L_ + (bc & (NC - 1)) * CHK;
    float v[64];
    #pragma unroll
    for (int l = 0; l < 64; l++)
        v[l] = g_zx[(size_t)(rowbase + l) * DIP + (DIP - NH) + h] + bias;
    #pragma unroll
    for (int l = 0; l < 64; l++)
        v[l] = softplusf(v[l]);
    float cum = 0.f;
    float* dsta = g_ac + ((size_t)bc * NH + h) * CHK;
    #pragma unroll
    for (int l = 0; l < 64; l++) {
        g_dt[(size_t)(rowbase + l) * NH + h] = v[l];
        cum += v[l] * A;
        dsta[l] = cum;
    }
}

// ---------------- chunk kernel: CB, Y_diag (+D*x), chunk states ----------------
// Padded smem strides (129 / 65); xs aliases Cs after CB. 2 CTAs/SM.
#define HGRP 4
#define HPB  (NH / HGRP)   // 16 heads per block
#define SP128 129
#define SP64  65
#define CHUNK_SMEM ((2*64*SP128 + 2*64*SP64 + 3*64) * 4)
__global__ void __launch_bounds__(256) chunk_kernel(const float* __restrict__ Dv)
{
    extern __shared__ float smf[];
    float* Bs  = smf;                    // [64][129]
    float* Cs  = Bs  + 64 * SP128;       // [64][129]  (reused as xs after CB)
    float* xs  = Cs;                     // alias [64][65]
    float* CB  = Cs  + 64 * SP128;       // [64][65]
    float* Lw  = CB  + 64 * SP64;        // [64][65]
    float* ac  = Lw  + 64 * SP64;        // [64]
    float* dtl = ac  + 64;               // [64]
    float* vv  = dtl + 64;               // [64]

    int bc  = blockIdx.x;
    int h0  = blockIdx.y * HPB;
    int tid = threadIdx.x;
    int rowbase = (bc >> 6) * L_ + (bc & (NC - 1)) * CHK;

    for (int i = tid; i < 64 * 32; i += 256) {
        int r  = i >> 5;
        int c4 = (i & 31) * 4;
        const float* rp = g_xbc + (size_t)(rowbase + r) * CDIM;
        float4 bv = *(const float4*)(rp + DSSM + c4);
        float4 cv = *(const float4*)(rp + DSSM + DST + c4);
        Bs[r * SP128 + c4 + 0] = bv.x; Bs[r * SP128 + c4 + 1] = bv.y;
        Bs[r * SP128 + c4 + 2] = bv.z; Bs[r * SP128 + c4 + 3] = bv.w;
        Cs[r * SP128 + c4 + 0] = cv.x; Cs[r * SP128 + c4 + 1] = cv.y;
        Cs[r * SP128 + c4 + 2] = cv.z; Cs[r * SP128 + c4 + 3] = cv.w;
    }
    __syncthreads();

    {
        int lt = (tid >> 4) * 4, st = (tid & 15) * 4;
        float acc[4][4];
        #pragma unroll
        for (int i = 0; i < 4; i++)
            #pragma unroll
            for (int j = 0; j < 4; j++) acc[i][j] = 0.f;
        for (int n = 0; n < 128; n++) {
            float a[4], b[4];
            #pragma unroll
            for (int i = 0; i < 4; i++) a[i] = Cs[(lt + i) * SP128 + n];
            #pragma unroll
            for (int j = 0; j < 4; j++) b[j] = Bs[(st + j) * SP128 + n];
            #pragma unroll
            for (int i = 0; i < 4; i++)
                #pragma unroll
                for (int j = 0; j < 4; j++) acc[i][j] += a[i] * b[j];
        }
        __syncthreads();   // CB write waits for all Cs reads (xs aliases Cs)
        #pragma unroll
        for (int i = 0; i < 4; i++)
            #pragma unroll
            for (int j = 0; j < 4; j++) CB[(lt + i) * SP64 + st + j] = acc[i][j];
    }
    __syncthreads();

    for (int hh = 0; hh < HPB; hh++) {
        int h = h0 + hh;
        for (int i = tid; i < 64 * 16; i += 256) {
            int r  = i >> 4;
            int c4 = (i & 15) * 4;
            float4 xv = *(const float4*)(g_xbc + (size_t)(rowbase + r) * CDIM + h * HD + c4);
            xs[r * SP64 + c4 + 0] = xv.x; xs[r * SP64 + c4 + 1] = xv.y;
            xs[r * SP64 + c4 + 2] = xv.z; xs[r * SP64 + c4 + 3] = xv.w;
        }
        if (tid < 64) {
            ac[tid]  = g_ac[((size_t)bc * NH + h) * CHK + tid];
            dtl[tid] = g_dt[(size_t)(rowbase + tid) * NH + h];
        }
        __syncthreads();
        if (tid < 64) vv[tid] = __expf(ac[63] - ac[tid]) * dtl[tid];
        for (int o = tid; o < 64 * 64; o += 256) {
            int l = o >> 6, s = o & 63;
            Lw[l * SP64 + s] = (s <= l) ? CB[l * SP64 + s] * __expf(ac[l] - ac[s]) * dtl[s] : 0.f;
        }
        __syncthreads();

        {
            int lt = (tid >> 4) * 4, pt = (tid & 15) * 4;
            float acc[4][4];
            #pragma unroll
            for (int i = 0; i < 4; i++)
                #pragma unroll
                for (int j = 0; j < 4; j++) acc[i][j] = 0.f;
            for (int s = 0; s < 64; s++) {
                float a[4], xb[4];
                #pragma unroll
                for (int i = 0; i < 4; i++) a[i] = Lw[(lt + i) * SP64 + s];
                #pragma unroll
                for (int j = 0; j < 4; j++) xb[j] = xs[s * SP64 + pt + j];
                #pragma unroll
                for (int i = 0; i < 4; i++)
                    #pragma unroll
                    for (int j = 0; j < 4; j++) acc[i][j] += a[i] * xb[j];
            }
            float Dh = Dv[h];
            #pragma unroll
            for (int i = 0; i < 4; i++) {
                int l = lt + i;
                size_t yrow = (size_t)(rowbase + l) * DSSM + h * HD;
                #pragma unroll
                for (int j = 0; j < 4; j++) {
                    int p = pt + j;
                    g_y[yrow + p] = acc[i][j] + Dh * xs[l * SP64 + p];
                }
            }
        }

        {
            int pr = (tid >> 4) * 4, ncn = (tid & 15) * 8;
            float acc[4][8];
            #pragma unroll
            for (int i = 0; i < 4; i++)
                #pragma unroll
                for (int j = 0; j < 8; j++) acc[i][j] = 0.f;
            for (int l = 0; l < 64; l++) {
                float w = vv[l];
                float xv[4], bn[8];
                #pragma unroll
                for (int i = 0; i < 4; i++) xv[i] = xs[l * SP64 + pr + i] * w;
                #pragma unroll
                for (int j = 0; j < 8; j++) bn[j] = Bs[l * SP128 + ncn + j];
                #pragma unroll
                for (int i = 0; i < 4; i++)
                    #pragma unroll
                    for (int j = 0; j < 8; j++) acc[i][j] += xv[i] * bn[j];
            }
            size_t sbase = ((size_t)bc * NH + h) * (HD * DST);
            #pragma unroll
            for (int i = 0; i < 4; i++)
                #pragma unroll
                for (int j = 0; j < 8; j += 4)
                    *(float4*)&g_st[sbase + (size_t)(pr + i) * DST + ncn + j] =
                        make_float4(acc[i][j], acc[i][j+1], acc[i][j+2], acc[i][j+3]);
        }
        __syncthreads();
    }
}

// ---------------- inter-chunk scan (in-place: states -> prev) ----------------
__global__ void __launch_bounds__(256) scan_kernel()
{
    int b = blockIdx.x >> 6;
    int h = blockIdx.x & (NH - 1);
    int k0 = blockIdx.y * 8;
    int tid = threadIdx.x;
    float carry[8];
    #pragma unroll
    for (int k = 0; k < 8; k++) carry[k] = 0.f;

    for (int c = 0; c < NC; c++) {
        int bc = b * NC + c;
        float cd = __expf(g_ac[((size_t)bc * NH + h) * CHK + (CHK - 1)]);
        size_t base = ((size_t)bc * NH + h) * (HD * DST) + (size_t)k0 * 256;
        #pragma unroll
        for (int k = 0; k < 8; k++) {
            size_t e = base + (size_t)k * 256 + tid;
            float s = g_st[e];
            g_st[e] = carry[k];
            carry[k] = carry[k] * cd + s;
        }
    }
}

// ---------------- Y_off: y += exp(Acum[l]) * (C[l] . prev[p]) ----------------
__global__ void __launch_bounds__(256) yoff_kernel()
{
    __shared__ float Ch[64 * SP64];
    __shared__ float Ph[64 * SP64];
    __shared__ float acs[64];

    int bc  = blockIdx.x;
    int h   = blockIdx.y;
    int tid = threadIdx.x;
    int rowbase = (bc >> 6) * L_ + (bc & (NC - 1)) * CHK;
    size_t sbase = ((size_t)bc * NH + h) * (HD * DST);

    if (tid < 64) acs[tid] = __expf(g_ac[((size_t)bc * NH + h) * CHK + tid]);

    int lt = (tid >> 4) * 4, pt = (tid & 15) * 4;
    float acc[4][4];
    #pragma unroll
    for (int i = 0; i < 4; i++)
        #pragma unroll
        for (int j = 0; j < 4; j++) acc[i][j] = 0.f;

    for (int half = 0; half < 2; half++) {
        __syncthreads();
        for (int i = tid; i < 64 * 16; i += 256) {
            int r  = i >> 4;
            int c4 = (i & 15) * 4;
            float4 cv = *(const float4*)(g_xbc + (size_t)(rowbase + r) * CDIM + DSSM + DST + half * 64 + c4);
            float4 pv = *(const float4*)(g_st + sbase + (size_t)r * DST + half * 64 + c4);
            Ch[r * SP64 + c4 + 0] = cv.x; Ch[r * SP64 + c4 + 1] = cv.y;
            Ch[r * SP64 + c4 + 2] = cv.z; Ch[r * SP64 + c4 + 3] = cv.w;
            Ph[r * SP64 + c4 + 0] = pv.x; Ph[r * SP64 + c4 + 1] = pv.y;
            Ph[r * SP64 + c4 + 2] = pv.z; Ph[r * SP64 + c4 + 3] = pv.w;
        }
        __syncthreads();
        for (int n = 0; n < 64; n++) {
            float a[4], p[4];
            #pragma unroll
            for (int i = 0; i < 4; i++) a[i] = Ch[(lt + i) * SP64 + n];
            #pragma unroll
            for (int j = 0; j < 4; j++) p[j] = Ph[(pt + j) * SP64 + n];
            #pragma unroll
            for (int i = 0; i < 4; i++)
                #pragma unroll
                for (int j = 0; j < 4; j++) acc[i][j] += a[i] * p[j];
        }
    }

    #pragma unroll
    for (int i = 0; i < 4; i++) {
        int l = lt + i;
        size_t yrow = (size_t)(rowbase + l) * DSSM + h * HD;
        float e = acs[l];
        #pragma unroll
        for (int j = 0; j < 4; j++)
            g_y[yrow + pt + j] += e * acc[i][j];
    }
}

// ---------------- gate (y * silu(z)) + RMSNorm -> fp16 split (ynh, ynl) ----------------
__global__ void __launch_bounds__(256) gatenorm_kernel(const float* __restrict__ nw)
{
    int row = blockIdx.x;
    int tid = threadIdx.x;
    float yg[16];
    float ss = 0.f;
    #pragma unroll
    for (int k = 0; k < 16; k++) {
        int i = k * 256 + tid;
        float y = g_y[(size_t)row * DSSM + i];
        float z = g_zx[(size_t)row * DIP + i];
        float v = y * siluf(z);
        yg[k] = v;
        ss += v * v;
    }
    __shared__ float red[256];
    red[tid] = ss;
    __syncthreads();
    for (int off = 128; off; off >>= 1) {
        if (tid < off) red[tid] += red[tid + off];
        __syncthreads();
    }
    float scale = rsqrtf(red[0] / (float)DSSM + 1e-5f);
    #pragma unroll
    for (int k = 0; k < 16; k++) {
        int i = k * 256 + tid;
        float t = yg[k] * scale * nw[i];
        __half h, l;
        split1(t, h, l);
        g_ynh[(size_t)row * DSSM + i] = h;
        g_ynl[(size_t)row * DSSM + i] = l;
    }
}

// ---------------- launch ----------------
extern "C" void kernel_launch(void* const* d_in, const int* in_sizes, int n_in,
                              void* d_out, int out_size)
{
    const float* u        = (const float*)d_in[0];
    const float* W_in     = (const float*)d_in[1];
    const float* conv_w   = (const float*)d_in[2];
    const float* conv_b   = (const float*)d_in[3];
    const float* dt_bias  = (const float*)d_in[4];
    const float* A_log    = (const float*)d_in[5];
    const float* Dv       = (const float*)d_in[6];
    const float* norm_w   = (const float*)d_in[7];
    const float* W_out    = (const float*)d_in[8];
    float* out = (float*)d_out;

    float* zx;
    cudaGetSymbolAddress((void**)&zx, g_zx);
    __half *uh, *ul, *w1h, *ynh, *ynl, *w2h;
    cudaGetSymbolAddress((void**)&uh,  g_uh);  cudaGetSymbolAddress((void**)&ul,  g_ul);
    cudaGetSymbolAddress((void**)&w1h, g_w1h);
    cudaGetSymbolAddress((void**)&ynh, g_ynh); cudaGetSymbolAddress((void**)&ynl, g_ynl);
    cudaGetSymbolAddress((void**)&w2h, g_w2h);

    cudaFuncSetAttribute(chunk_kernel,
                         cudaFuncAttributeMaxDynamicSharedMemorySize, CHUNK_SMEM);
    cudaFuncSetAttribute(gemm_fp16x2,
                         cudaFuncAttributeMaxDynamicSharedMemorySize, GSMEM);

    // 0. split fp32 operands into fp16
    {
        int n1 = BL * DM;          // u (hi+lo)
        int n2 = DIP * DM;         // W_in (hi only)
        int n3 = DM * DSSM;        // W_out (hi only)
        split2_kernel<<<(n1 / 4 + 255) / 256, 256>>>(u, uh, ul, n1);
        splith_kernel<<<(n2 / 4 + 255) / 256, 256>>>(W_in, w1h, n2);
        splith_kernel<<<(n3 / 4 + 255) / 256, 256>>>(W_out, w2h, n3);
    }

    // 1. zxbcdt = u @ W_in^T   [8192 x 8512] via fp16x2 mma
    {
        int tilesM = BL / 128, tilesN = (DIP + 127) / 128;  // 64 x 67
        gemm_fp16x2<<<tilesM * tilesN, 256, GSMEM>>>(uh, ul, w1h, zx,
                                                     BL, DIP, DM, tilesN, 8);
    }
    // 2. conv + silu (sliding window)
    conv_silu_kernel<<<dim3((CDIM + 255) / 256, BL / 64), 256>>>(conv_w, conv_b);
    // 3+4. fused softplus(dt) + per-chunk A cumsum
    acum_kernel<<<B_ * NC, 64>>>(A_log, dt_bias);
    // 5. chunk-local: CB, Y_diag(+Dx), states  (4 head-groups)
    chunk_kernel<<<dim3(B_ * NC, HGRP), 256, CHUNK_SMEM>>>(Dv);
    // 6. inter-chunk scan (4 k-groups)
    scan_kernel<<<dim3(B_ * NH, 4), 256>>>();
    // 7. Y_off accumulate
    yoff_kernel<<<dim3(B_ * NC, NH), 256>>>();
    // 8. gate + RMSNorm -> fp16 split
    gatenorm_kernel<<<BL, 256>>>(norm_w);
    // 9. out = yn @ W_out^T   [8192 x 2048] via fp16x2 mma
    {
        int tilesM = BL / 128, tilesN = DM / 128;  // 64 x 16
        gemm_fp16x2<<<tilesM * tilesN, 256, GSMEM>>>(ynh, ynl, w2h, out,
                                                     BL, DM, DSSM, tilesN, 8);
    }
}

// round 16
// speedup vs baseline: 2.6487x; 1.0625x over previous
#include <cuda_runtime.h>
#include <cuda_fp16.h>
#include <cstdint>

// ---------------- problem constants ----------------
#define B_    2
#define L_    4096
#define DM    2048      // d_model
#define DSSM  4096
#define DST   128       // d_state
#define NH    64        // heads
#define HD    64        // headdim
#define DCONV 4
#define CHK   64        // chunk length
#define NC    64        // num chunks (L/CHK)
#define DIP   8512      // d_in_proj
#define CDIM  4352      // conv dim
#define BL    8192      // B_*L_

// ---------------- scratch (static device, allocation-free) ----------------
__device__ float g_zx [69730304];   // [BL][DIP]        zxbcdt
__device__ float g_xbc[35651584];   // [BL][CDIM]       conv+silu output
__device__ float g_dt [524288];     // [BL][NH]         softplus(dt)
__device__ float g_ac [524288];     // [b*NC][NH][CHK]  A_cum within chunk
__device__ float g_st [67108864];   // [b*NC][NH][DST][HD]  states (n-major!) -> prev
__device__ float g_y  [33554432];   // [BL][DSSM]       y before gate/norm

// fp16 split operands for tensor-core GEMMs (A = h + l, B = h only)
__device__ __half g_uh [16777216], g_ul [16777216];   // u      [BL][DM]
__device__ __half g_w1h[17432576];                    // W_in   [DIP][DM]
__device__ __half g_ynh[33554432], g_ynl[33554432];   // yn     [BL][DSSM]
__device__ __half g_w2h[ 8388608];                    // W_out  [DM][DSSM]

// ---------------- helpers ----------------
__device__ __forceinline__ float siluf(float x) {
    return x / (1.f + __expf(-x));
}
__device__ __forceinline__ float softplusf(float x) {
    return x > 20.f ? x : log1pf(__expf(x));
}
__device__ __forceinline__ void split1(float x, __half& h, __half& l) {
    h = __float2half_rn(x);
    l = __float2half_rn(x - __half2float(h));
}

// ---------------- cp.async / ldmatrix / mma helpers ----------------
__device__ __forceinline__ void cp16(uint32_t dst, const void* src) {
    asm volatile("cp.async.cg.shared.global [%0], [%1], 16;\n" :: "r"(dst), "l"(src));
}
__device__ __forceinline__ void cp16z(uint32_t dst, const void* src, int sz) {
    asm volatile("cp.async.cg.shared.global [%0], [%1], 16, %2;\n"
                 :: "r"(dst), "l"(src), "r"(sz));
}
#define CP_COMMIT() asm volatile("cp.async.commit_group;\n" ::: "memory")
#define CP_WAIT2()  asm volatile("cp.async.wait_group 2;\n" ::: "memory")
#define CP_WAIT0()  asm volatile("cp.async.wait_group 0;\n" ::: "memory")

__device__ __forceinline__ void ldsm4(uint32_t* r, uint32_t addr) {
    asm volatile("ldmatrix.sync.aligned.m8n8.x4.shared.b16 {%0,%1,%2,%3}, [%4];"
                 : "=r"(r[0]), "=r"(r[1]), "=r"(r[2]), "=r"(r[3]) : "r"(addr));
}
__device__ __forceinline__ void mma_fp16(float* c, const uint32_t* a, const uint32_t* b) {
    asm volatile(
        "mma.sync.aligned.m16n8k16.row.col.f32.f16.f16.f32 "
        "{%0,%1,%2,%3}, {%4,%5,%6,%7}, {%8,%9}, {%0,%1,%2,%3};\n"
        : "+f"(c[0]), "+f"(c[1]), "+f"(c[2]), "+f"(c[3])
        : "r"(a[0]), "r"(a[1]), "r"(a[2]), "r"(a[3]), "r"(b[0]), "r"(b[1]));
}

// ---------------- fp32 -> fp16 (hi, lo) split ----------------
__global__ void split2_kernel(const float* __restrict__ src,
                              __half* __restrict__ h,
                              __half* __restrict__ l, int n)
{
    int i = (blockIdx.x * blockDim.x + threadIdx.x) * 4;
    if (i >= n) return;
    float4 v = *(const float4*)(src + i);
    __half hh[4], ll[4];
    split1(v.x, hh[0], ll[0]); split1(v.y, hh[1], ll[1]);
    split1(v.z, hh[2], ll[2]); split1(v.w, hh[3], ll[3]);
    *(uint2*)(h + i) = *(uint2*)hh;
    *(uint2*)(l + i) = *(uint2*)ll;
}

// ---------------- fp32 -> fp16 (hi only) ----------------
__global__ void splith_kernel(const float* __restrict__ src,
                              __half* __restrict__ h, int n)
{
    int i = (blockIdx.x * blockDim.x + threadIdx.x) * 4;
    if (i >= n) return;
    float4 v = *(const float4*)(src + i);
    __half hh[4];
    hh[0] = __float2half_rn(v.x); hh[1] = __float2half_rn(v.y);
    hh[2] = __float2half_rn(v.z); hh[3] = __float2half_rn(v.w);
    *(uint2*)(h + i) = *(uint2*)hh;
}

// ---------------- fp16x2 mma.sync GEMM (R15 measured-best; FROZEN) ----------------
#define MATB   8192
#define STAGEB 24576
#define NSTG   4
#define GSMEM  98304
__global__ void __launch_bounds__(256, 2) gemm_fp16x2(
    const __half* __restrict__ Ah, const __half* __restrict__ Al,
    const __half* __restrict__ Bh,
    float* __restrict__ C, int M, int Nn, int K, int tilesN, int group)
{
    extern __shared__ char smc[];
    uint32_t sb = (uint32_t)__cvta_generic_to_shared(smc);

    int tid = threadIdx.x;
    int wid = tid >> 5, lane = tid & 31;
    int wm = wid & 3, wn = wid >> 2;
    int g = lane >> 2, kt = lane & 3;

    int tilesM = M >> 7;
    int pid = blockIdx.x;
    int gsize = group * tilesN;
    int gid = pid / gsize;
    int first = gid * group;
    int gsz = min(group, tilesM - first);
    int rem = pid - gid * gsize;
    int pm = first + rem % gsz;
    int pn = rem / gsz;
    int bm = pm << 7, bn = pn << 7;

    float acc[2][8][4];
    #pragma unroll
    for (int mt = 0; mt < 2; mt++)
        #pragma unroll
        for (int nt = 0; nt < 8; nt++)
            #pragma unroll
            for (int q = 0; q < 4; q++) acc[mt][nt][q] = 0.f;

    int niter = K >> 5;

    auto load_stage = [&](int st, int k0) {
        #pragma unroll
        for (int t = 0; t < 6; t++) {
            int mat = t >> 1;
            int idx = ((t & 1) << 8) + tid;
            int row = idx >> 2, c = idx & 3;
            uint32_t dst = sb + st * STAGEB + mat * MATB + row * 64
                         + (((c ^ (row >> 1)) & 3) << 4);
            if (mat < 2) {
                const __half* s =
                    (mat == 0 ? Ah : Al) + (size_t)(bm + row) * K + k0 + c * 8;
                cp16(dst, s);
            } else {
                int br = bn + row;
                int ok = (br < Nn) ? 16 : 0;
                const __half* s = Bh + (size_t)(ok ? br : 0) * K + k0 + c * 8;
                cp16z(dst, s, ok);
            }
        }
        CP_COMMIT();
    };

    load_stage(0, 0);
    load_stage(1, 32);
    load_stage(2, 64);

    int lrA = lane & 15, hcA = lane >> 4;
    int lrB = ((lane >> 4) << 3) + (lane & 7), hcB = (lane >> 3) & 1;

    for (int it = 0; it < niter; it++) {
        if (it + 1 < niter) { CP_WAIT2(); } else { CP_WAIT0(); }
        __syncthreads();

        uint32_t abase = sb + (it & (NSTG - 1)) * STAGEB;

        {
            uint32_t bh[4][4];
            #pragma unroll
            for (int p = 0; p < 4; p++) {
                int rB = wn * 64 + p * 16 + lrB;
                ldsm4(bh[p], abase + 2 * MATB + rB * 64
                             + (((hcB ^ (rB >> 1)) & 3) << 4));
            }
            #pragma unroll
            for (int mt = 0; mt < 2; mt++) {
                int rA = wm * 32 + mt * 16 + lrA;
                uint32_t ad = abase + rA * 64 + (((hcA ^ (rA >> 1)) & 3) << 4);
                uint32_t ah[4], al[4];
                ldsm4(ah, ad);
                ldsm4(al, ad + MATB);
                #pragma unroll
                for (int nt = 0; nt < 8; nt++) {
                    const uint32_t* fh = &bh[nt >> 1][(nt & 1) * 2];
                    mma_fp16(acc[mt][nt], ah, fh);
                    mma_fp16(acc[mt][nt], al, fh);
                }
            }
        }

        if (it + 3 < niter) load_stage((it + 3) & (NSTG - 1), (it + 3) << 5);
        else CP_COMMIT();

        {
            uint32_t bh[4][4];
            #pragma unroll
            for (int p = 0; p < 4; p++) {
                int rB = wn * 64 + p * 16 + lrB;
                ldsm4(bh[p], abase + 2 * MATB + rB * 64
                             + ((((2 + hcB) ^ (rB >> 1)) & 3) << 4));
            }
            #pragma unroll
            for (int mt = 0; mt < 2; mt++) {
                int rA = wm * 32 + mt * 16 + lrA;
                uint32_t ad = abase + rA * 64
                            + ((((2 + hcA) ^ (rA >> 1)) & 3) << 4);
                uint32_t ah[4], al[4];
                ldsm4(ah, ad);
                ldsm4(al, ad + MATB);
                #pragma unroll
                for (int nt = 0; nt < 8; nt++) {
                    const uint32_t* fh = &bh[nt >> 1][(nt & 1) * 2];
                    mma_fp16(acc[mt][nt], ah, fh);
                    mma_fp16(acc[mt][nt], al, fh);
                }
            }
        }
    }

    #pragma unroll
    for (int mt = 0; mt < 2; mt++) {
        int row = bm + wm * 32 + mt * 16 + g;
        #pragma unroll
        for (int nt = 0; nt < 8; nt++) {
            int col = bn + wn * 64 + nt * 8 + 2 * kt;
            if (col < Nn) {
                *(float2*)(C + (size_t)row * Nn + col) =
                    make_float2(acc[mt][nt][0], acc[mt][nt][1]);
                *(float2*)(C + (size_t)(row + 8) * Nn + col) =
                    make_float2(acc[mt][nt][2], acc[mt][nt][3]);
            }
        }
    }
}

// ---------------- causal depthwise conv (width 4) + bias + SiLU ----------------
__global__ void __launch_bounds__(256) conv_silu_kernel(
    const float* __restrict__ conv_w, const float* __restrict__ conv_b)
{
    int ch = blockIdx.x * 256 + threadIdx.x;
    if (ch >= CDIM) return;
    int lt = blockIdx.y;
    int bl0 = lt * 64;
    int l0 = bl0 & (L_ - 1);

    float w0 = conv_w[ch * 4 + 0], w1 = conv_w[ch * 4 + 1];
    float w2 = conv_w[ch * 4 + 2], w3 = conv_w[ch * 4 + 3];
    float bi = conv_b[ch];

    const float* src = g_zx + DSSM + ch;
    float x0 = (l0 >= 3) ? src[(size_t)(bl0 - 3) * DIP] : 0.f;
    float x1 = (l0 >= 2) ? src[(size_t)(bl0 - 2) * DIP] : 0.f;
    float x2 = (l0 >= 1) ? src[(size_t)(bl0 - 1) * DIP] : 0.f;

    float* dst = g_xbc + (size_t)bl0 * CDIM + ch;
    #pragma unroll 8
    for (int k = 0; k < 64; k++) {
        float x3 = src[(size_t)(bl0 + k) * DIP];
        float s = bi + w0 * x0 + w1 * x1 + w2 * x2 + w3 * x3;
        dst[(size_t)k * CDIM] = siluf(s);
        x0 = x1; x1 = x2; x2 = x3;
    }
}

// ---------------- fused softplus(dt) + per-chunk cumsum of dA = dt*A ----------------
__global__ void acum_kernel(const float* __restrict__ A_log,
                            const float* __restrict__ dt_bias)
{
    int bc = blockIdx.x;
    int h  = threadIdx.x;
    float A = -expf(A_log[h]);
    float bias = dt_bias[h];
    int rowbase = (bc >> 6) * L_ + (bc & (NC - 1)) * CHK;
    float v[64];
    #pragma unroll
    for (int l = 0; l < 64; l++)
        v[l] = g_zx[(size_t)(rowbase + l) * DIP + (DIP - NH) + h] + bias;
    #pragma unroll
    for (int l = 0; l < 64; l++)
        v[l] = softplusf(v[l]);
    float cum = 0.f;
    float* dsta = g_ac + ((size_t)bc * NH + h) * CHK;
    #pragma unroll
    for (int l = 0; l < 64; l++) {
        g_dt[(size_t)(rowbase + l) * NH + h] = v[l];
        cum += v[l] * A;
        dsta[l] = cum;
    }
}

// ---------------- chunk kernel: CB, Y_diag (+D*x), chunk states ----------------
// Changes vs R15: Lw via multiplicative recurrence (64 exps instead of 4096),
// fused Y_diag+states k-loop sharing xs reads, stride-68 vectorized xs/Lw tiles,
// states written to g_st in [n][p] layout (coalesced float4).
#define HGRP 4
#define HPB  (NH / HGRP)   // 16 heads per block
#define SP128 129
#define SPX   68
#define CHUNK_SMEM ((2*64*SP128 + 2*64*SPX + 4*64) * 4)
__global__ void __launch_bounds__(256) chunk_kernel(const float* __restrict__ Dv)
{
    extern __shared__ float smf[];
    float* Bs  = smf;                    // [64][129]
    float* Cs  = Bs  + 64 * SP128;       // [64][129]  (reused as xs after CB)
    float* xs  = Cs;                     // alias [64][68]
    float* CB  = Cs  + 64 * SP128;       // [64][68]
    float* Lw  = CB  + 64 * SPX;         // [64][68]
    float* ac  = Lw  + 64 * SPX;         // [64]
    float* dtl = ac  + 64;               // [64]
    float* vv  = dtl + 64;               // [64]
    float* edA = vv  + 64;               // [64]

    int bc  = blockIdx.x;
    int h0  = blockIdx.y * HPB;
    int tid = threadIdx.x;
    int rowbase = (bc >> 6) * L_ + (bc & (NC - 1)) * CHK;

    for (int i = tid; i < 64 * 32; i += 256) {
        int r  = i >> 5;
        int c4 = (i & 31) * 4;
        const float* rp = g_xbc + (size_t)(rowbase + r) * CDIM;
        float4 bv = *(const float4*)(rp + DSSM + c4);
        float4 cv = *(const float4*)(rp + DSSM + DST + c4);
        Bs[r * SP128 + c4 + 0] = bv.x; Bs[r * SP128 + c4 + 1] = bv.y;
        Bs[r * SP128 + c4 + 2] = bv.z; Bs[r * SP128 + c4 + 3] = bv.w;
        Cs[r * SP128 + c4 + 0] = cv.x; Cs[r * SP128 + c4 + 1] = cv.y;
        Cs[r * SP128 + c4 + 2] = cv.z; Cs[r * SP128 + c4 + 3] = cv.w;
    }
    __syncthreads();

    {
        int lt = (tid >> 4) * 4, st = (tid & 15) * 4;
        float acc[4][4];
        #pragma unroll
        for (int i = 0; i < 4; i++)
            #pragma unroll
            for (int j = 0; j < 4; j++) acc[i][j] = 0.f;
        for (int n = 0; n < 128; n++) {
            float a[4], b[4];
            #pragma unroll
            for (int i = 0; i < 4; i++) a[i] = Cs[(lt + i) * SP128 + n];
            #pragma unroll
            for (int j = 0; j < 4; j++) b[j] = Bs[(st + j) * SP128 + n];
            #pragma unroll
            for (int i = 0; i < 4; i++)
                #pragma unroll
                for (int j = 0; j < 4; j++) acc[i][j] += a[i] * b[j];
        }
        __syncthreads();   // CB write waits for all Cs reads (xs aliases Cs)
        #pragma unroll
        for (int i = 0; i < 4; i++)
            #pragma unroll
            for (int j = 0; j < 4; j++) CB[(lt + i) * SPX + st + j] = acc[i][j];
    }
    __syncthreads();

    for (int hh = 0; hh < HPB; hh++) {
        int h = h0 + hh;
        for (int i = tid; i < 64 * 16; i += 256) {
            int r  = i >> 4;
            int c4 = (i & 15) * 4;
            float4 xv = *(const float4*)(g_xbc + (size_t)(rowbase + r) * CDIM + h * HD + c4);
            *(float4*)&xs[r * SPX + c4] = xv;
        }
        if (tid < 64) {
            ac[tid]  = g_ac[((size_t)bc * NH + h) * CHK + tid];
            dtl[tid] = g_dt[(size_t)(rowbase + tid) * NH + h];
        }
        __syncthreads();
        if (tid < 64) vv[tid] = __expf(ac[63] - ac[tid]) * dtl[tid];
        else if (tid < 128) {
            int l = tid - 64;
            edA[l] = (l == 0) ? 1.f : __expf(ac[l] - ac[l - 1]);
        }
        __syncthreads();
        // Lw via recurrence: Lw[l][s] = CB[l][s] * dt[s] * prod_{j=s+1..l} edA[j]
        if (tid < 64) {
            int s = tid;
            float w = dtl[s];
            for (int l = 0; l < 64; l++) {
                float val = 0.f;
                if (l >= s) {
                    if (l > s) w *= edA[l];
                    val = CB[l * SPX + s] * w;
                }
                Lw[l * SPX + s] = val;
            }
        }
        __syncthreads();

        // fused Y_diag + states k-loop (shared xs reads)
        {
            int lt = (tid >> 4) * 4;        // Y_diag row group
            int pt = (tid & 15) * 4;        // shared p group
            int ncn = (tid >> 4) * 8;       // states n group
            float ay[4][4], as_[4][8];
            #pragma unroll
            for (int i = 0; i < 4; i++) {
                #pragma unroll
                for (int j = 0; j < 4; j++) ay[i][j] = 0.f;
                #pragma unroll
                for (int j = 0; j < 8; j++) as_[i][j] = 0.f;
            }
            for (int k = 0; k < 64; k++) {
                float4 b4 = *(const float4*)&xs[k * SPX + pt];
                float b[4] = {b4.x, b4.y, b4.z, b4.w};
                float a[4];
                #pragma unroll
                for (int i = 0; i < 4; i++) a[i] = Lw[(lt + i) * SPX + k];
                float w = vv[k];
                float bn[8];
                #pragma unroll
                for (int j = 0; j < 8; j++) bn[j] = Bs[k * SP128 + ncn + j];
                float xv[4];
                #pragma unroll
                for (int i = 0; i < 4; i++) xv[i] = b[i] * w;
                #pragma unroll
                for (int i = 0; i < 4; i++)
                    #pragma unroll
                    for (int j = 0; j < 4; j++) ay[i][j] += a[i] * b[j];
                #pragma unroll
                for (int i = 0; i < 4; i++)
                    #pragma unroll
                    for (int j = 0; j < 8; j++) as_[i][j] += xv[i] * bn[j];
            }
            // write Y_diag + D*x
            float Dh = Dv[h];
            #pragma unroll
            for (int i = 0; i < 4; i++) {
                int l = lt + i;
                float4 xd = *(const float4*)&xs[l * SPX + pt];
                float4 o = make_float4(ay[i][0] + Dh * xd.x, ay[i][1] + Dh * xd.y,
                                       ay[i][2] + Dh * xd.z, ay[i][3] + Dh * xd.w);
                *(float4*)(g_y + (size_t)(rowbase + l) * DSSM + h * HD + pt) = o;
            }
            // write states: g_st layout [bc][h][n][p]
            size_t sbase = ((size_t)bc * NH + h) * (HD * DST);
            #pragma unroll
            for (int j = 0; j < 8; j++) {
                float4 o = make_float4(as_[0][j], as_[1][j], as_[2][j], as_[3][j]);
                *(float4*)(g_st + sbase + (size_t)(ncn + j) * HD + pt) = o;
            }
        }
        __syncthreads();
    }
}

// ---------------- inter-chunk scan (in-place, layout-agnostic flat) ----------------
__global__ void __launch_bounds__(256) scan_kernel()
{
    int b = blockIdx.x >> 6;
    int h = blockIdx.x & (NH - 1);
    int k0 = blockIdx.y * 8;
    int tid = threadIdx.x;
    float carry[8];
    #pragma unroll
    for (int k = 0; k < 8; k++) carry[k] = 0.f;

    for (int c = 0; c < NC; c++) {
        int bc = b * NC + c;
        float cd = __expf(g_ac[((size_t)bc * NH + h) * CHK + (CHK - 1)]);
        size_t base = ((size_t)bc * NH + h) * (HD * DST) + (size_t)k0 * 256;
        #pragma unroll
        for (int k = 0; k < 8; k++) {
            size_t e = base + (size_t)k * 256 + tid;
            float s = g_st[e];
            g_st[e] = carry[k];
            carry[k] = carry[k] * cd + s;
        }
    }
}

// ---------------- Y_off: y += exp(Acum[l]) * (C[l] . prev[:, p]) ----------------
// prev stored [n][p]: PhT tile loads are coalesced and p-reads vectorized.
__global__ void __launch_bounds__(256) yoff_kernel()
{
    __shared__ float Ch [64 * SPX];
    __shared__ float PhT[64 * SPX];
    __shared__ float acs[64];

    int bc  = blockIdx.x;
    int h   = blockIdx.y;
    int tid = threadIdx.x;
    int rowbase = (bc >> 6) * L_ + (bc & (NC - 1)) * CHK;
    size_t sbase = ((size_t)bc * NH + h) * (HD * DST);

    if (tid < 64) acs[tid] = __expf(g_ac[((size_t)bc * NH + h) * CHK + tid]);

    int lt = (tid >> 4) * 4, pt = (tid & 15) * 4;
    float acc[4][4];
    #pragma unroll
    for (int i = 0; i < 4; i++)
        #pragma unroll
        for (int j = 0; j < 4; j++) acc[i][j] = 0.f;

    for (int half = 0; half < 2; half++) {
        __syncthreads();
        for (int i = tid; i < 64 * 16; i += 256) {
            int r  = i >> 4;
            int c4 = (i & 15) * 4;
            float4 cv = *(const float4*)(g_xbc + (size_t)(rowbase + r) * CDIM + DSSM + DST + half * 64 + c4);
            float4 pv = *(const float4*)(g_st + sbase + (size_t)(half * 64 + r) * HD + c4);
            *(float4*)&Ch [r * SPX + c4] = cv;
            *(float4*)&PhT[r * SPX + c4] = pv;
        }
        __syncthreads();
        for (int n = 0; n < 64; n++) {
            float a[4];
            #pragma unroll
            for (int i = 0; i < 4; i++) a[i] = Ch[(lt + i) * SPX + n];
            float4 p4 = *(const float4*)&PhT[n * SPX + pt];
            float p[4] = {p4.x, p4.y, p4.z, p4.w};
            #pragma unroll
            for (int i = 0; i < 4; i++)
                #pragma unroll
                for (int j = 0; j < 4; j++) acc[i][j] += a[i] * p[j];
        }
    }

    #pragma unroll
    for (int i = 0; i < 4; i++) {
        int l = lt + i;
        float e = acs[l];
        float* yp = g_y + (size_t)(rowbase + l) * DSSM + h * HD + pt;
        float4 cur = *(float4*)yp;
        cur.x += e * acc[i][0]; cur.y += e * acc[i][1];
        cur.z += e * acc[i][2]; cur.w += e * acc[i][3];
        *(float4*)yp = cur;
    }
}

// ---------------- gate (y * silu(z)) + RMSNorm -> fp16 split (ynh, ynl) ----------------
__global__ void __launch_bounds__(256) gatenorm_kernel(const float* __restrict__ nw)
{
    int row = blockIdx.x;
    int tid = threadIdx.x;
    float yg[16];
    float ss = 0.f;
    #pragma unroll
    for (int k = 0; k < 16; k++) {
        int i = k * 256 + tid;
        float y = g_y[(size_t)row * DSSM + i];
        float z = g_zx[(size_t)row * DIP + i];
        float v = y * siluf(z);
        yg[k] = v;
        ss += v * v;
    }
    __shared__ float red[256];
    red[tid] = ss;
    __syncthreads();
    for (int off = 128; off; off >>= 1) {
        if (tid < off) red[tid] += red[tid + off];
        __syncthreads();
    }
    float scale = rsqrtf(red[0] / (float)DSSM + 1e-5f);
    #pragma unroll
    for (int k = 0; k < 16; k++) {
        int i = k * 256 + tid;
        float t = yg[k] * scale * nw[i];
        __half h, l;
        split1(t, h, l);
        g_ynh[(size_t)row * DSSM + i] = h;
        g_ynl[(size_t)row * DSSM + i] = l;
    }
}

// ---------------- launch ----------------
extern "C" void kernel_launch(void* const* d_in, const int* in_sizes, int n_in,
                              void* d_out, int out_size)
{
    const float* u        = (const float*)d_in[0];
    const float* W_in     = (const float*)d_in[1];
    const float* conv_w   = (const float*)d_in[2];
    const float* conv_b   = (const float*)d_in[3];
    const float* dt_bias  = (const float*)d_in[4];
    const float* A_log    = (const float*)d_in[5];
    const float* Dv       = (const float*)d_in[6];
    const float* norm_w   = (const float*)d_in[7];
    const float* W_out    = (const float*)d_in[8];
    float* out = (float*)d_out;

    float* zx;
    cudaGetSymbolAddress((void**)&zx, g_zx);
    __half *uh, *ul, *w1h, *ynh, *ynl, *w2h;
    cudaGetSymbolAddress((void**)&uh,  g_uh);  cudaGetSymbolAddress((void**)&ul,  g_ul);
    cudaGetSymbolAddress((void**)&w1h, g_w1h);
    cudaGetSymbolAddress((void**)&ynh, g_ynh); cudaGetSymbolAddress((void**)&ynl, g_ynl);
    cudaGetSymbolAddress((void**)&w2h, g_w2h);

    cudaFuncSetAttribute(chunk_kernel,
                         cudaFuncAttributeMaxDynamicSharedMemorySize, CHUNK_SMEM);
    cudaFuncSetAttribute(gemm_fp16x2,
                         cudaFuncAttributeMaxDynamicSharedMemorySize, GSMEM);

    // 0. split fp32 operands into fp16
    {
        int n1 = BL * DM;          // u (hi+lo)
        int n2 = DIP * DM;         // W_in (hi only)
        int n3 = DM * DSSM;        // W_out (hi only)
        split2_kernel<<<(n1 / 4 + 255) / 256, 256>>>(u, uh, ul, n1);
        splith_kernel<<<(n2 / 4 + 255) / 256, 256>>>(W_in, w1h, n2);
        splith_kernel<<<(n3 / 4 + 255) / 256, 256>>>(W_out, w2h, n3);
    }

    // 1. zxbcdt = u @ W_in^T   [8192 x 8512] via fp16x2 mma
    {
        int tilesM = BL / 128, tilesN = (DIP + 127) / 128;  // 64 x 67
        gemm_fp16x2<<<tilesM * tilesN, 256, GSMEM>>>(uh, ul, w1h, zx,
                                                     BL, DIP, DM, tilesN, 8);
    }
    // 2. conv + silu (sliding window)
    conv_silu_kernel<<<dim3((CDIM + 255) / 256, BL / 64), 256>>>(conv_w, conv_b);
    // 3+4. fused softplus(dt) + per-chunk A cumsum
    acum_kernel<<<B_ * NC, 64>>>(A_log, dt_bias);
    // 5. chunk-local: CB, Y_diag(+Dx), states  (4 head-groups)
    chunk_kernel<<<dim3(B_ * NC, HGRP), 256, CHUNK_SMEM>>>(Dv);
    // 6. inter-chunk scan (4 k-groups)
    scan_kernel<<<dim3(B_ * NH, 4), 256>>>();
    // 7. Y_off accumulate
    yoff_kernel<<<dim3(B_ * NC, NH), 256>>>();
    // 8. gate + RMSNorm -> fp16 split
    gatenorm_kernel<<<BL, 256>>>(norm_w);
    // 9. out = yn @ W_out^T   [8192 x 2048] via fp16x2 mma
    {
        int tilesM = BL / 128, tilesN = DM / 128;  // 64 x 16
        gemm_fp16x2<<<tilesM * tilesN, 256, GSMEM>>>(ynh, ynl, w2h, out,
                                                     BL, DM, DSSM, tilesN, 8);
    }
}

// round 17
// speedup vs baseline: 3.4374x; 1.2978x over previous
#include <cuda_runtime.h>
#include <cuda_fp16.h>
#include <cstdint>

// ---------------- problem constants ----------------
#define B_    2
#define L_    4096
#define DM    2048      // d_model
#define DSSM  4096
#define DST   128       // d_state
#define NH    64        // heads
#define HD    64        // headdim
#define DCONV 4
#define CHK   64        // chunk length
#define NC    64        // num chunks (L/CHK)
#define DIP   8512      // d_in_proj
#define CDIM  4352      // conv dim
#define BL    8192      // B_*L_

// ---------------- scratch (static device, allocation-free) ----------------
__device__ float g_zx [69730304];   // [BL][DIP]        zxbcdt
__device__ float g_xbc[35651584];   // [BL][CDIM]       conv+silu output
__device__ float g_dt [524288];     // [BL][NH]         softplus(dt)
__device__ float g_ac [524288];     // [b*NC][NH][CHK]  A_cum within chunk
__device__ __half g_st[67108864];   // [b*NC][NH][DST][HD]  states fp16 (n-major) -> prev
__device__ float g_y  [33554432];   // [BL][DSSM]       y before gate/norm

// fp16 split operands for tensor-core GEMMs (A = h + l, B = h only)
__device__ __half g_uh [16777216], g_ul [16777216];   // u      [BL][DM]
__device__ __half g_w1h[17432576];                    // W_in   [DIP][DM]
__device__ __half g_ynh[33554432], g_ynl[33554432];   // yn     [BL][DSSM]
__device__ __half g_w2h[ 8388608];                    // W_out  [DM][DSSM]

// ---------------- helpers ----------------
__device__ __forceinline__ float siluf(float x) {
    return x / (1.f + __expf(-x));
}
__device__ __forceinline__ float softplusf(float x) {
    return x > 20.f ? x : log1pf(__expf(x));
}
__device__ __forceinline__ void split1(float x, __half& h, __half& l) {
    h = __float2half_rn(x);
    l = __float2half_rn(x - __half2float(h));
}

// ---------------- cp.async / ldmatrix / mma helpers ----------------
__device__ __forceinline__ void cp16(uint32_t dst, const void* src) {
    asm volatile("cp.async.cg.shared.global [%0], [%1], 16;\n" :: "r"(dst), "l"(src));
}
__device__ __forceinline__ void cp16z(uint32_t dst, const void* src, int sz) {
    asm volatile("cp.async.cg.shared.global [%0], [%1], 16, %2;\n"
                 :: "r"(dst), "l"(src), "r"(sz));
}
#define CP_COMMIT() asm volatile("cp.async.commit_group;\n" ::: "memory")
#define CP_WAIT2()  asm volatile("cp.async.wait_group 2;\n" ::: "memory")
#define CP_WAIT0()  asm volatile("cp.async.wait_group 0;\n" ::: "memory")

__device__ __forceinline__ void ldsm4(uint32_t* r, uint32_t addr) {
    asm volatile("ldmatrix.sync.aligned.m8n8.x4.shared.b16 {%0,%1,%2,%3}, [%4];"
                 : "=r"(r[0]), "=r"(r[1]), "=r"(r[2]), "=r"(r[3]) : "r"(addr));
}
__device__ __forceinline__ void mma_fp16(float* c, const uint32_t* a, const uint32_t* b) {
    asm volatile(
        "mma.sync.aligned.m16n8k16.row.col.f32.f16.f16.f32 "
        "{%0,%1,%2,%3}, {%4,%5,%6,%7}, {%8,%9}, {%0,%1,%2,%3};\n"
        : "+f"(c[0]), "+f"(c[1]), "+f"(c[2]), "+f"(c[3])
        : "r"(a[0]), "r"(a[1]), "r"(a[2]), "r"(a[3]), "r"(b[0]), "r"(b[1]));
}

// ---------------- fp32 -> fp16 (hi, lo) split ----------------
__global__ void split2_kernel(const float* __restrict__ src,
                              __half* __restrict__ h,
                              __half* __restrict__ l, int n)
{
    int i = (blockIdx.x * blockDim.x + threadIdx.x) * 4;
    if (i >= n) return;
    float4 v = *(const float4*)(src + i);
    __half hh[4], ll[4];
    split1(v.x, hh[0], ll[0]); split1(v.y, hh[1], ll[1]);
    split1(v.z, hh[2], ll[2]); split1(v.w, hh[3], ll[3]);
    *(uint2*)(h + i) = *(uint2*)hh;
    *(uint2*)(l + i) = *(uint2*)ll;
}

// ---------------- fp32 -> fp16 (hi only) ----------------
__global__ void splith_kernel(const float* __restrict__ src,
                              __half* __restrict__ h, int n)
{
    int i = (blockIdx.x * blockDim.x + threadIdx.x) * 4;
    if (i >= n) return;
    float4 v = *(const float4*)(src + i);
    __half hh[4];
    hh[0] = __float2half_rn(v.x); hh[1] = __float2half_rn(v.y);
    hh[2] = __float2half_rn(v.z); hh[3] = __float2half_rn(v.w);
    *(uint2*)(h + i) = *(uint2*)hh;
}

// ---------------- fp16x2 mma.sync GEMM (R15 measured-best; FROZEN) ----------------
#define MATB   8192
#define STAGEB 24576
#define NSTG   4
#define GSMEM  98304
__global__ void __launch_bounds__(256, 2) gemm_fp16x2(
    const __half* __restrict__ Ah, const __half* __restrict__ Al,
    const __half* __restrict__ Bh,
    float* __restrict__ C, int M, int Nn, int K, int tilesN, int group)
{
    extern __shared__ char smc[];
    uint32_t sb = (uint32_t)__cvta_generic_to_shared(smc);

    int tid = threadIdx.x;
    int wid = tid >> 5, lane = tid & 31;
    int wm = wid & 3, wn = wid >> 2;
    int g = lane >> 2, kt = lane & 3;

    int tilesM = M >> 7;
    int pid = blockIdx.x;
    int gsize = group * tilesN;
    int gid = pid / gsize;
    int first = gid * group;
    int gsz = min(group, tilesM - first);
    int rem = pid - gid * gsize;
    int pm = first + rem % gsz;
    int pn = rem / gsz;
    int bm = pm << 7, bn = pn << 7;

    float acc[2][8][4];
    #pragma unroll
    for (int mt = 0; mt < 2; mt++)
        #pragma unroll
        for (int nt = 0; nt < 8; nt++)
            #pragma unroll
            for (int q = 0; q < 4; q++) acc[mt][nt][q] = 0.f;

    int niter = K >> 5;

    auto load_stage = [&](int st, int k0) {
        #pragma unroll
        for (int t = 0; t < 6; t++) {
            int mat = t >> 1;
            int idx = ((t & 1) << 8) + tid;
            int row = idx >> 2, c = idx & 3;
            uint32_t dst = sb + st * STAGEB + mat * MATB + row * 64
                         + (((c ^ (row >> 1)) & 3) << 4);
            if (mat < 2) {
                const __half* s =
                    (mat == 0 ? Ah : Al) + (size_t)(bm + row) * K + k0 + c * 8;
                cp16(dst, s);
            } else {
                int br = bn + row;
                int ok = (br < Nn) ? 16 : 0;
                const __half* s = Bh + (size_t)(ok ? br : 0) * K + k0 + c * 8;
                cp16z(dst, s, ok);
            }
        }
        CP_COMMIT();
    };

    load_stage(0, 0);
    load_stage(1, 32);
    load_stage(2, 64);

    int lrA = lane & 15, hcA = lane >> 4;
    int lrB = ((lane >> 4) << 3) + (lane & 7), hcB = (lane >> 3) & 1;

    for (int it = 0; it < niter; it++) {
        if (it + 1 < niter) { CP_WAIT2(); } else { CP_WAIT0(); }
        __syncthreads();

        uint32_t abase = sb + (it & (NSTG - 1)) * STAGEB;

        {
            uint32_t bh[4][4];
            #pragma unroll
            for (int p = 0; p < 4; p++) {
                int rB = wn * 64 + p * 16 + lrB;
                ldsm4(bh[p], abase + 2 * MATB + rB * 64
                             + (((hcB ^ (rB >> 1)) & 3) << 4));
            }
            #pragma unroll
            for (int mt = 0; mt < 2; mt++) {
                int rA = wm * 32 + mt * 16 + lrA;
                uint32_t ad = abase + rA * 64 + (((hcA ^ (rA >> 1)) & 3) << 4);
                uint32_t ah[4], al[4];
                ldsm4(ah, ad);
                ldsm4(al, ad + MATB);
                #pragma unroll
                for (int nt = 0; nt < 8; nt++) {
                    const uint32_t* fh = &bh[nt >> 1][(nt & 1) * 2];
                    mma_fp16(acc[mt][nt], ah, fh);
                    mma_fp16(acc[mt][nt], al, fh);
                }
            }
        }

        if (it + 3 < niter) load_stage((it + 3) & (NSTG - 1), (it + 3) << 5);
        else CP_COMMIT();

        {
            uint32_t bh[4][4];
            #pragma unroll
            for (int p = 0; p < 4; p++) {
                int rB = wn * 64 + p * 16 + lrB;
                ldsm4(bh[p], abase + 2 * MATB + rB * 64
                             + ((((2 + hcB) ^ (rB >> 1)) & 3) << 4));
            }
            #pragma unroll
            for (int mt = 0; mt < 2; mt++) {
                int rA = wm * 32 + mt * 16 + lrA;
                uint32_t ad = abase + rA * 64
                            + ((((2 + hcA) ^ (rA >> 1)) & 3) << 4);
                uint32_t ah[4], al[4];
                ldsm4(ah, ad);
                ldsm4(al, ad + MATB);
                #pragma unroll
                for (int nt = 0; nt < 8; nt++) {
                    const uint32_t* fh = &bh[nt >> 1][(nt & 1) * 2];
                    mma_fp16(acc[mt][nt], ah, fh);
                    mma_fp16(acc[mt][nt], al, fh);
                }
            }
        }
    }

    #pragma unroll
    for (int mt = 0; mt < 2; mt++) {
        int row = bm + wm * 32 + mt * 16 + g;
        #pragma unroll
        for (int nt = 0; nt < 8; nt++) {
            int col = bn + wn * 64 + nt * 8 + 2 * kt;
            if (col < Nn) {
                *(float2*)(C + (size_t)row * Nn + col) =
                    make_float2(acc[mt][nt][0], acc[mt][nt][1]);
                *(float2*)(C + (size_t)(row + 8) * Nn + col) =
                    make_float2(acc[mt][nt][2], acc[mt][nt][3]);
            }
        }
    }
}

// ---------------- causal depthwise conv (width 4) + bias + SiLU ----------------
__global__ void __launch_bounds__(256) conv_silu_kernel(
    const float* __restrict__ conv_w, const float* __restrict__ conv_b)
{
    int ch = blockIdx.x * 256 + threadIdx.x;
    if (ch >= CDIM) return;
    int lt = blockIdx.y;
    int bl0 = lt * 64;
    int l0 = bl0 & (L_ - 1);

    float w0 = conv_w[ch * 4 + 0], w1 = conv_w[ch * 4 + 1];
    float w2 = conv_w[ch * 4 + 2], w3 = conv_w[ch * 4 + 3];
    float bi = conv_b[ch];

    const float* src = g_zx + DSSM + ch;
    float x0 = (l0 >= 3) ? src[(size_t)(bl0 - 3) * DIP] : 0.f;
    float x1 = (l0 >= 2) ? src[(size_t)(bl0 - 2) * DIP] : 0.f;
    float x2 = (l0 >= 1) ? src[(size_t)(bl0 - 1) * DIP] : 0.f;

    float* dst = g_xbc + (size_t)bl0 * CDIM + ch;
    #pragma unroll 8
    for (int k = 0; k < 64; k++) {
        float x3 = src[(size_t)(bl0 + k) * DIP];
        float s = bi + w0 * x0 + w1 * x1 + w2 * x2 + w3 * x3;
        dst[(size_t)k * CDIM] = siluf(s);
        x0 = x1; x1 = x2; x2 = x3;
    }
}

// ---------------- fused softplus(dt) + per-chunk cumsum of dA = dt*A ----------------
__global__ void acum_kernel(const float* __restrict__ A_log,
                            const float* __restrict__ dt_bias)
{
    int bc = blockIdx.x;
    int h  = threadIdx.x;
    float A = -expf(A_log[h]);
    float bias = dt_bias[h];
    int rowbase = (bc >> 6) * L_ + (bc & (NC - 1)) * CHK;
    float v[64];
    #pragma unroll
    for (int l = 0; l < 64; l++)
        v[l] = g_zx[(size_t)(rowbase + l) * DIP + (DIP - NH) + h] + bias;
    #pragma unroll
    for (int l = 0; l < 64; l++)
        v[l] = softplusf(v[l]);
    float cum = 0.f;
    float* dsta = g_ac + ((size_t)bc * NH + h) * CHK;
    #pragma unroll
    for (int l = 0; l < 64; l++) {
        g_dt[(size_t)(rowbase + l) * NH + h] = v[l];
        cum += v[l] * A;
        dsta[l] = cum;
    }
}

// ---------------- chunk kernel: CB, Y_diag (+D*x), chunk states ----------------
// R16 structure; states epilogue now stores fp16 [n][p] (half2 pairs).
#define HGRP 4
#define HPB  (NH / HGRP)   // 16 heads per block
#define SP128 129
#define SPX   68
#define CHUNK_SMEM ((2*64*SP128 + 2*64*SPX + 4*64) * 4)
__global__ void __launch_bounds__(256) chunk_kernel(const float* __restrict__ Dv)
{
    extern __shared__ float smf[];
    float* Bs  = smf;                    // [64][129]
    float* Cs  = Bs  + 64 * SP128;       // [64][129]  (reused as xs after CB)
    float* xs  = Cs;                     // alias [64][68]
    float* CB  = Cs  + 64 * SP128;       // [64][68]
    float* Lw  = CB  + 64 * SPX;         // [64][68]
    float* ac  = Lw  + 64 * SPX;         // [64]
    float* dtl = ac  + 64;               // [64]
    float* vv  = dtl + 64;               // [64]
    float* edA = vv  + 64;               // [64]

    int bc  = blockIdx.x;
    int h0  = blockIdx.y * HPB;
    int tid = threadIdx.x;
    int rowbase = (bc >> 6) * L_ + (bc & (NC - 1)) * CHK;

    for (int i = tid; i < 64 * 32; i += 256) {
        int r  = i >> 5;
        int c4 = (i & 31) * 4;
        const float* rp = g_xbc + (size_t)(rowbase + r) * CDIM;
        float4 bv = *(const float4*)(rp + DSSM + c4);
        float4 cv = *(const float4*)(rp + DSSM + DST + c4);
        Bs[r * SP128 + c4 + 0] = bv.x; Bs[r * SP128 + c4 + 1] = bv.y;
        Bs[r * SP128 + c4 + 2] = bv.z; Bs[r * SP128 + c4 + 3] = bv.w;
        Cs[r * SP128 + c4 + 0] = cv.x; Cs[r * SP128 + c4 + 1] = cv.y;
        Cs[r * SP128 + c4 + 2] = cv.z; Cs[r * SP128 + c4 + 3] = cv.w;
    }
    __syncthreads();

    {
        int lt = (tid >> 4) * 4, st = (tid & 15) * 4;
        float acc[4][4];
        #pragma unroll
        for (int i = 0; i < 4; i++)
            #pragma unroll
            for (int j = 0; j < 4; j++) acc[i][j] = 0.f;
        for (int n = 0; n < 128; n++) {
            float a[4], b[4];
            #pragma unroll
            for (int i = 0; i < 4; i++) a[i] = Cs[(lt + i) * SP128 + n];
            #pragma unroll
            for (int j = 0; j < 4; j++) b[j] = Bs[(st + j) * SP128 + n];
            #pragma unroll
            for (int i = 0; i < 4; i++)
                #pragma unroll
                for (int j = 0; j < 4; j++) acc[i][j] += a[i] * b[j];
        }
        __syncthreads();   // CB write waits for all Cs reads (xs aliases Cs)
        #pragma unroll
        for (int i = 0; i < 4; i++)
            #pragma unroll
            for (int j = 0; j < 4; j++) CB[(lt + i) * SPX + st + j] = acc[i][j];
    }
    __syncthreads();

    for (int hh = 0; hh < HPB; hh++) {
        int h = h0 + hh;
        for (int i = tid; i < 64 * 16; i += 256) {
            int r  = i >> 4;
            int c4 = (i & 15) * 4;
            float4 xv = *(const float4*)(g_xbc + (size_t)(rowbase + r) * CDIM + h * HD + c4);
            *(float4*)&xs[r * SPX + c4] = xv;
        }
        if (tid < 64) {
            ac[tid]  = g_ac[((size_t)bc * NH + h) * CHK + tid];
            dtl[tid] = g_dt[(size_t)(rowbase + tid) * NH + h];
        }
        __syncthreads();
        if (tid < 64) vv[tid] = __expf(ac[63] - ac[tid]) * dtl[tid];
        else if (tid < 128) {
            int l = tid - 64;
            edA[l] = (l == 0) ? 1.f : __expf(ac[l] - ac[l - 1]);
        }
        __syncthreads();
        // Lw via recurrence: Lw[l][s] = CB[l][s] * dt[s] * prod_{j=s+1..l} edA[j]
        if (tid < 64) {
            int s = tid;
            float w = dtl[s];
            for (int l = 0; l < 64; l++) {
                float val = 0.f;
                if (l >= s) {
                    if (l > s) w *= edA[l];
                    val = CB[l * SPX + s] * w;
                }
                Lw[l * SPX + s] = val;
            }
        }
        __syncthreads();

        // fused Y_diag + states k-loop (shared xs reads)
        {
            int lt = (tid >> 4) * 4;        // Y_diag row group
            int pt = (tid & 15) * 4;        // shared p group
            int ncn = (tid >> 4) * 8;       // states n group
            float ay[4][4], as_[4][8];
            #pragma unroll
            for (int i = 0; i < 4; i++) {
                #pragma unroll
                for (int j = 0; j < 4; j++) ay[i][j] = 0.f;
                #pragma unroll
                for (int j = 0; j < 8; j++) as_[i][j] = 0.f;
            }
            for (int k = 0; k < 64; k++) {
                float4 b4 = *(const float4*)&xs[k * SPX + pt];
                float b[4] = {b4.x, b4.y, b4.z, b4.w};
                float a[4];
                #pragma unroll
                for (int i = 0; i < 4; i++) a[i] = Lw[(lt + i) * SPX + k];
                float w = vv[k];
                float bn[8];
                #pragma unroll
                for (int j = 0; j < 8; j++) bn[j] = Bs[k * SP128 + ncn + j];
                float xv[4];
                #pragma unroll
                for (int i = 0; i < 4; i++) xv[i] = b[i] * w;
                #pragma unroll
                for (int i = 0; i < 4; i++)
                    #pragma unroll
                    for (int j = 0; j < 4; j++) ay[i][j] += a[i] * b[j];
                #pragma unroll
                for (int i = 0; i < 4; i++)
                    #pragma unroll
                    for (int j = 0; j < 8; j++) as_[i][j] += xv[i] * bn[j];
            }
            // write Y_diag + D*x
            float Dh = Dv[h];
            #pragma unroll
            for (int i = 0; i < 4; i++) {
                int l = lt + i;
                float4 xd = *(const float4*)&xs[l * SPX + pt];
                float4 o = make_float4(ay[i][0] + Dh * xd.x, ay[i][1] + Dh * xd.y,
                                       ay[i][2] + Dh * xd.z, ay[i][3] + Dh * xd.w);
                *(float4*)(g_y + (size_t)(rowbase + l) * DSSM + h * HD + pt) = o;
            }
            // write states fp16: g_st layout [bc][h][n][p]
            size_t sbase = ((size_t)bc * NH + h) * (HD * DST);
            #pragma unroll
            for (int j = 0; j < 8; j++) {
                __half2 o0 = __floats2half2_rn(as_[0][j], as_[1][j]);
                __half2 o1 = __floats2half2_rn(as_[2][j], as_[3][j]);
                uint2 pk;
                pk.x = *(uint32_t*)&o0;
                pk.y = *(uint32_t*)&o1;
                *(uint2*)(g_st + sbase + (size_t)(ncn + j) * HD + pt) = pk;
            }
        }
        __syncthreads();
    }
}

// ---------------- inter-chunk scan (in-place, fp16 storage, fp32 carry) ----------------
__global__ void __launch_bounds__(256) scan_kernel()
{
    int b = blockIdx.x >> 6;
    int h = blockIdx.x & (NH - 1);
    int ky = blockIdx.y;            // 0..3
    int tid = threadIdx.x;
    float carry[8];
    #pragma unroll
    for (int k = 0; k < 8; k++) carry[k] = 0.f;

    for (int c = 0; c < NC; c++) {
        int bc = b * NC + c;
        float cd = __expf(g_ac[((size_t)bc * NH + h) * CHK + (CHK - 1)]);
        __half2* base = (__half2*)g_st + ((size_t)bc * NH + h) * 4096 + ky * 1024;
        #pragma unroll
        for (int k = 0; k < 4; k++) {
            __half2 v = base[k * 256 + tid];
            float s0 = __low2float(v), s1 = __high2float(v);
            base[k * 256 + tid] = __floats2half2_rn(carry[2 * k], carry[2 * k + 1]);
            carry[2 * k]     = carry[2 * k]     * cd + s0;
            carry[2 * k + 1] = carry[2 * k + 1] * cd + s1;
        }
    }
}

// ---------------- Y_off via fp16 mma: y += exp(Acum[l]) * (Ch[l][n] . prev[n][p]) ----
// A = Ch[l][n] (64x128 fp16), B = PT[p][n] (64x128 fp16, transposed prev).
// Mirrors the big-GEMM fragment addressing (padded 136-half rows, conflict-free).
#define YP 136
__global__ void __launch_bounds__(256) yoff_kernel()
{
    __shared__ __half Ch[64 * YP];
    __shared__ __half PT[64 * YP];
    __shared__ float acs[64];

    int bc  = blockIdx.x;
    int h   = blockIdx.y;
    int tid = threadIdx.x;
    int wid = tid >> 5, lane = tid & 31;
    int wm = wid & 3, wn = wid >> 2;     // 4 M-tiles (16), 2 N-tiles (32)
    int g = lane >> 2, kt = lane & 3;
    int rowbase = (bc >> 6) * L_ + (bc & (NC - 1)) * CHK;
    size_t sbase = ((size_t)bc * NH + h) * (HD * DST);   // in halves

    if (tid < 64) acs[tid] = __expf(g_ac[((size_t)bc * NH + h) * CHK + tid]);

    // fill Ch[l][n] from g_xbc fp32 (convert to fp16)
    for (int i = tid; i < 64 * 32; i += 256) {
        int r = i >> 5, c4 = (i & 31) * 4;
        float4 cv = *(const float4*)(g_xbc + (size_t)(rowbase + r) * CDIM + DSSM + DST + c4);
        __half hh[4];
        hh[0] = __float2half_rn(cv.x); hh[1] = __float2half_rn(cv.y);
        hh[2] = __float2half_rn(cv.z); hh[3] = __float2half_rn(cv.w);
        *(uint2*)&Ch[r * YP + c4] = *(uint2*)hh;
    }
    // fill PT[p][n] transposed from g_st fp16 [n][p]
    for (int i = tid; i < 128 * 32; i += 256) {
        int n = i >> 5, pp = (i & 31) * 2;
        __half2 v = *(const __half2*)(g_st + sbase + (size_t)n * HD + pp);
        PT[pp * YP + n]       = __low2half(v);
        PT[(pp + 1) * YP + n] = __high2half(v);
    }
    __syncthreads();

    float acc[4][4];
    #pragma unroll
    for (int nt = 0; nt < 4; nt++)
        #pragma unroll
        for (int q = 0; q < 4; q++) acc[nt][q] = 0.f;

    uint32_t chb = (uint32_t)__cvta_generic_to_shared(Ch);
    uint32_t ptb = (uint32_t)__cvta_generic_to_shared(PT);
    int lrA = lane & 15, hcA = lane >> 4;
    int lrB = ((lane >> 4) << 3) + (lane & 7), hcB = (lane >> 3) & 1;

    #pragma unroll
    for (int kk = 0; kk < 8; kk++) {
        uint32_t af[4];
        ldsm4(af, chb + ((wm * 16 + lrA) * YP + (kk * 2 + hcA) * 8) * 2);
        uint32_t bf[2][4];
        #pragma unroll
        for (int p = 0; p < 2; p++)
            ldsm4(bf[p], ptb + ((wn * 32 + p * 16 + lrB) * YP + (kk * 2 + hcB) * 8) * 2);
        #pragma unroll
        for (int nt = 0; nt < 4; nt++)
            mma_fp16(acc[nt], af, &bf[nt >> 1][(nt & 1) * 2]);
    }

    // epilogue: y += acs[l] * acc
    int row0 = wm * 16 + g;
    #pragma unroll
    for (int nt = 0; nt < 4; nt++) {
        int col = wn * 32 + nt * 8 + 2 * kt;
        {
            int l = row0;
            float e = acs[l];
            float* yp = g_y + (size_t)(rowbase + l) * DSSM + h * HD + col;
            float2 cur = *(float2*)yp;
            cur.x += e * acc[nt][0]; cur.y += e * acc[nt][1];
            *(float2*)yp = cur;
        }
        {
            int l = row0 + 8;
            float e = acs[l];
            float* yp = g_y + (size_t)(rowbase + l) * DSSM + h * HD + col;
            float2 cur = *(float2*)yp;
            cur.x += e * acc[nt][2]; cur.y += e * acc[nt][3];
            *(float2*)yp = cur;
        }
    }
}

// ---------------- gate (y * silu(z)) + RMSNorm -> fp16 split (ynh, ynl) ----------------
__global__ void __launch_bounds__(256) gatenorm_kernel(const float* __restrict__ nw)
{
    int row = blockIdx.x;
    int tid = threadIdx.x;
    float yg[16];
    float ss = 0.f;
    #pragma unroll
    for (int k = 0; k < 16; k++) {
        int i = k * 256 + tid;
        float y = g_y[(size_t)row * DSSM + i];
        float z = g_zx[(size_t)row * DIP + i];
        float v = y * siluf(z);
        yg[k] = v;
        ss += v * v;
    }
    __shared__ float red[256];
    red[tid] = ss;
    __syncthreads();
    for (int off = 128; off; off >>= 1) {
        if (tid < off) red[tid] += red[tid + off];
        __syncthreads();
    }
    float scale = rsqrtf(red[0] / (float)DSSM + 1e-5f);
    #pragma unroll
    for (int k = 0; k < 16; k++) {
        int i = k * 256 + tid;
        float t = yg[k] * scale * nw[i];
        __half h, l;
        split1(t, h, l);
        g_ynh[(size_t)row * DSSM + i] = h;
        g_ynl[(size_t)row * DSSM + i] = l;
    }
}

// ---------------- launch ----------------
extern "C" void kernel_launch(void* const* d_in, const int* in_sizes, int n_in,
                              void* d_out, int out_size)
{
    const float* u        = (const float*)d_in[0];
    const float* W_in     = (const float*)d_in[1];
    const float* conv_w   = (const float*)d_in[2];
    const float* conv_b   = (const float*)d_in[3];
    const float* dt_bias  = (const float*)d_in[4];
    const float* A_log    = (const float*)d_in[5];
    const float* Dv       = (const float*)d_in[6];
    const float* norm_w   = (const float*)d_in[7];
    const float* W_out    = (const float*)d_in[8];
    float* out = (float*)d_out;

    float* zx;
    cudaGetSymbolAddress((void**)&zx, g_zx);
    __half *uh, *ul, *w1h, *ynh, *ynl, *w2h;
    cudaGetSymbolAddress((void**)&uh,  g_uh);  cudaGetSymbolAddress((void**)&ul,  g_ul);
    cudaGetSymbolAddress((void**)&w1h, g_w1h);
    cudaGetSymbolAddress((void**)&ynh, g_ynh); cudaGetSymbolAddress((void**)&ynl, g_ynl);
    cudaGetSymbolAddress((void**)&w2h, g_w2h);

    cudaFuncSetAttribute(chunk_kernel,
                         cudaFuncAttributeMaxDynamicSharedMemorySize, CHUNK_SMEM);
    cudaFuncSetAttribute(gemm_fp16x2,
                         cudaFuncAttributeMaxDynamicSharedMemorySize, GSMEM);

    // 0. split fp32 operands into fp16
    {
        int n1 = BL * DM;          // u (hi+lo)
        int n2 = DIP * DM;         // W_in (hi only)
        int n3 = DM * DSSM;        // W_out (hi only)
        split2_kernel<<<(n1 / 4 + 255) / 256, 256>>>(u, uh, ul, n1);
        splith_kernel<<<(n2 / 4 + 255) / 256, 256>>>(W_in, w1h, n2);
        splith_kernel<<<(n3 / 4 + 255) / 256, 256>>>(W_out, w2h, n3);
    }

    // 1. zxbcdt = u @ W_in^T   [8192 x 8512] via fp16x2 mma
    {
        int tilesM = BL / 128, tilesN = (DIP + 127) / 128;  // 64 x 67
        gemm_fp16x2<<<tilesM * tilesN, 256, GSMEM>>>(uh, ul, w1h, zx,
                                                     BL, DIP, DM, tilesN, 8);
    }
    // 2. conv + silu (sliding window)
    conv_silu_kernel<<<dim3((CDIM + 255) / 256, BL / 64), 256>>>(conv_w, conv_b);
    // 3+4. fused softplus(dt) + per-chunk A cumsum
    acum_kernel<<<B_ * NC, 64>>>(A_log, dt_bias);
    // 5. chunk-local: CB, Y_diag(+Dx), states  (4 head-groups)
    chunk_kernel<<<dim3(B_ * NC, HGRP), 256, CHUNK_SMEM>>>(Dv);
    // 6. inter-chunk scan (4 k-groups, fp16 storage)
    scan_kernel<<<dim3(B_ * NH, 4), 256>>>();
    // 7. Y_off accumulate via fp16 mma
    yoff_kernel<<<dim3(B_ * NC, NH), 256>>>();
    // 8. gate + RMSNorm -> fp16 split
    gatenorm_kernel<<<BL, 256>>>(norm_w);
    // 9. out = yn @ W_out^T   [8192 x 2048] via fp16x2 mma
    {
        int tilesM = BL / 128, tilesN = DM / 128;  // 64 x 16
        gemm_fp16x2<<<tilesM * tilesN, 256, GSMEM>>>(ynh, ynl, w2h, out,
                                                     BL, DM, DSSM, tilesN, 8);
    }
}